// round 11
// baseline (speedup 1.0000x reference)
#include <cuda_runtime.h>
#include <cstdint>

// Fused sparse-UNet backbone, round 11: 3xTF32 mma.sync, rebalanced tiles.
// Warp tile = 32 rows x N/2 cols (2 m16 tiles share every B-frag; half the
// n-tiles per warp) -> 40 LDS vs 48 HMMA per warp-8k at N=128 (was 68:48).
// CTA = 128 threads / 64 rows / ~99KB smem -> 2 CTAs/SM overlap sync bubbles.
// Scratch is CTA-shared; epilogues are two-phase (compute -> sync -> store).

#define THREADS 128
#define MROWS   64
#define PW      260                    // scratch pitch (floats), ==4 mod 32
#define KC      32                     // k-chunk
#define PNMAX   (128 + 8)
#define OFF_WHI 0
#define OFF_WLO (KC * PNMAX)           // 4352
#define OFF_SCR (2 * KC * PNMAX)       // 8704
#define SMEM_FLOATS (OFF_SCR + MROWS * PW)
#define SMEM_BYTES  (SMEM_FLOATS * 4)  // 101376 B

__device__ __forceinline__ uint32_t tf32r(float x){
    uint32_t r; asm("cvt.rna.tf32.f32 %0, %1;" : "=r"(r) : "f"(x)); return r;
}
__device__ __forceinline__ float frelu(float v){ return v > 0.f ? v : 0.f; }

__device__ __forceinline__ void mma8(float* d, const uint32_t* a, const uint32_t* b){
    asm volatile("mma.sync.aligned.m16n8k8.row.col.f32.tf32.tf32.f32 "
        "{%0,%1,%2,%3},{%4,%5,%6,%7},{%8,%9},{%0,%1,%2,%3};"
        : "+f"(d[0]), "+f"(d[1]), "+f"(d[2]), "+f"(d[3])
        : "r"(a[0]), "r"(a[1]), "r"(a[2]), "r"(a[3]), "r"(b[0]), "r"(b[1]));
}

// Warp (rg, cgh): rows [rg*32, rg*32+32) as 2 m16 tiles, cols [cgh*N/2, +N/2).
// EPI: 0 -> scratch ; 1 -> +pairsum(cat) -> scratch ; 2 -> gmem [*,32].
template<int K, int N, int EPI, bool ESAVE>
__device__ __forceinline__ void stage(const float* __restrict__ Wg,
                                      float* __restrict__ smem,
                                      int aBase, int dBase,
                                      float* __restrict__ eSave,
                                      float* __restrict__ gout,
                                      int growCta, int Ntot, int tid)
{
    constexpr int PN  = N + 8;               // weight pitch, ==8 mod 32
    constexpr int Nw  = N / 2;               // cols per warp
    constexpr int NTw = Nw / 8;              // n8-tiles per warp
    constexpr int KcC = (K < KC) ? K : KC;
    constexpr int NCH = K / KcC;
    const int lane = tid & 31;
    const int warp = tid >> 5;
    const int rg   = warp >> 1;              // row group (0,1)
    const int cgh  = warp & 1;               // col half (0,1)
    const int rbase = rg * 32;
    const int qr = lane >> 2, qc = lane & 3;
    float* scr = smem + OFF_SCR;

    float acc[2][NTw][4];
#pragma unroll
    for (int t = 0; t < 2; t++)
#pragma unroll
        for (int j = 0; j < NTw; j++){ acc[t][j][0]=acc[t][j][1]=acc[t][j][2]=acc[t][j][3]=0.f; }

    for (int ch = 0; ch < NCH; ch++){
        const int k0 = ch * KcC;
        __syncthreads();                     // weight buf free / prev stores visible
        {
            const float* wsrc = Wg + (size_t)k0 * N;
            for (int i = tid; i < KcC * N; i += THREADS){
                const int k = i / N, n = i % N;       // N pow2 -> shifts
                float w = wsrc[i];
                float hv = __uint_as_float(tf32r(w));
                smem[OFF_WHI + k * PN + n] = hv;
                smem[OFF_WLO + k * PN + n] = __uint_as_float(tf32r(w - hv));
            }
        }
        __syncthreads();

#pragma unroll
        for (int s = 0; s < KcC / 8; s++){
            const int kcol = aBase + k0 + 8 * s + qc;
            uint32_t ah[2][4], al[2][4];
#pragma unroll
            for (int t = 0; t < 2; t++){
                const float* rp = scr + (rbase + t * 16 + qr) * PW + kcol;
                float a0 = rp[0], a1 = rp[8 * PW], a2 = rp[4], a3 = rp[8 * PW + 4];
                ah[t][0] = tf32r(a0); ah[t][1] = tf32r(a1);
                ah[t][2] = tf32r(a2); ah[t][3] = tf32r(a3);
                al[t][0] = tf32r(a0 - __uint_as_float(ah[t][0]));
                al[t][1] = tf32r(a1 - __uint_as_float(ah[t][1]));
                al[t][2] = tf32r(a2 - __uint_as_float(ah[t][2]));
                al[t][3] = tf32r(a3 - __uint_as_float(ah[t][3]));
            }
            const float* bh = smem + OFF_WHI + (8 * s + qc) * PN + cgh * Nw + qr;
            const float* bl = smem + OFF_WLO + (8 * s + qc) * PN + cgh * Nw + qr;
#pragma unroll
            for (int j = 0; j < NTw; j++){
                uint32_t bhi[2] = { __float_as_uint(bh[8 * j]),
                                    __float_as_uint(bh[4 * PN + 8 * j]) };
                uint32_t blo[2] = { __float_as_uint(bl[8 * j]),
                                    __float_as_uint(bl[4 * PN + 8 * j]) };
                mma8(acc[0][j], ah[0], bhi);
                mma8(acc[0][j], ah[0], blo);
                mma8(acc[0][j], al[0], bhi);
                mma8(acc[1][j], ah[1], bhi);
                mma8(acc[1][j], ah[1], blo);
                mma8(acc[1][j], al[1], bhi);
            }
        }
    }

    // phase 1: relu (+red) into acc, all scratch READS done here
#pragma unroll
    for (int t = 0; t < 2; t++)
#pragma unroll
        for (int j = 0; j < NTw; j++){
            float v0 = frelu(acc[t][j][0]), v1 = frelu(acc[t][j][1]);
            float v2 = frelu(acc[t][j][2]), v3 = frelu(acc[t][j][3]);
            if constexpr (EPI == 1){
                const int cc = aBase + 2 * cgh * Nw + 16 * j + 4 * qc;
                const float4 qa = *(const float4*)&scr[(rbase + t*16 + qr) * PW + cc];
                const float4 qb = *(const float4*)&scr[(rbase + t*16 + qr + 8) * PW + cc];
                v0 += qa.x + qa.y;  v1 += qa.z + qa.w;
                v2 += qb.x + qb.y;  v3 += qb.z + qb.w;
            }
            if constexpr (ESAVE){
                float* e = eSave + (t * NTw + j) * 4;
                e[0] = v0; e[1] = v1; e[2] = v2; e[3] = v3;
            }
            acc[t][j][0] = v0; acc[t][j][1] = v1; acc[t][j][2] = v2; acc[t][j][3] = v3;
        }

    if constexpr (EPI == 2){
#pragma unroll
        for (int t = 0; t < 2; t++)
#pragma unroll
            for (int j = 0; j < NTw; j++){
                const int col = cgh * Nw + 8 * j + 2 * qc;
                const int g0 = growCta + rbase + t * 16 + qr;
                if (g0 < Ntot)
                    *(float2*)&gout[(size_t)g0 * 32 + col] = make_float2(acc[t][j][0], acc[t][j][1]);
                if (g0 + 8 < Ntot)
                    *(float2*)&gout[(size_t)(g0 + 8) * 32 + col] = make_float2(acc[t][j][2], acc[t][j][3]);
            }
        return;
    }

    __syncthreads();                         // all reads done -> safe to overwrite
#pragma unroll
    for (int t = 0; t < 2; t++)
#pragma unroll
        for (int j = 0; j < NTw; j++){
            const int col = dBase + cgh * Nw + 8 * j + 2 * qc;
            float* r0 = &scr[(rbase + t*16 + qr) * PW + col];
            float* r1 = &scr[(rbase + t*16 + qr + 8) * PW + col];
            *(float2*)r0 = make_float2(acc[t][j][0], acc[t][j][1]);
            *(float2*)r1 = make_float2(acc[t][j][2], acc[t][j][3]);
        }
}

// write saved e-regs back to scratch at channel base (same mapping as stores)
template<int N>
__device__ __forceinline__ void restage(float* __restrict__ scr, int base,
                                        const float* __restrict__ e, int tid){
    constexpr int Nw = N / 2, NTw = Nw / 8;
    const int lane = tid & 31, warp = tid >> 5;
    const int rg = warp >> 1, cgh = warp & 1;
    const int rbase = rg * 32;
    const int qr = lane >> 2, qc = lane & 3;
#pragma unroll
    for (int t = 0; t < 2; t++)
#pragma unroll
        for (int j = 0; j < NTw; j++){
            const float* ep = e + (t * NTw + j) * 4;
            const int col = base + cgh * Nw + 8 * j + 2 * qc;
            *(float2*)&scr[(rbase + t*16 + qr) * PW + col]     = make_float2(ep[0], ep[1]);
            *(float2*)&scr[(rbase + t*16 + qr + 8) * PW + col] = make_float2(ep[2], ep[3]);
        }
}

__global__ void __launch_bounds__(THREADS, 2)
backbone_mma(const float* __restrict__ feat,
             const float* __restrict__ Win,
             const float* __restrict__ We1, const float* __restrict__ We2,
             const float* __restrict__ We3,
             const float* __restrict__ Wl1, const float* __restrict__ Wl2,
             const float* __restrict__ Wl3,
             const float* __restrict__ Wm1, const float* __restrict__ Wm2,
             const float* __restrict__ Wm3,
             const float* __restrict__ Wu1, const float* __restrict__ Wu2,
             const float* __restrict__ Wu3,
             float* __restrict__ out, int Ntot)
{
    extern __shared__ float smem[];
    float* scr = smem + OFF_SCR;
    const int tid = threadIdx.x;
    const int growCta = blockIdx.x * MROWS;

    // feat[64 rows, 16 ch] -> scratch ch0-15
    {
        const int r = tid >> 1, h = tid & 1;
        const int g = growCta + r;
        float4 f0 = make_float4(0,0,0,0), f1 = f0;
        if (g < Ntot){
            const float4* src = (const float4*)&feat[(size_t)g * 16 + h * 8];
            f0 = src[0]; f1 = src[1];
        }
        *(float4*)&scr[r * PW + h * 8]     = f0;
        *(float4*)&scr[r * PW + h * 8 + 4] = f1;
    }
    // (first stage's leading __syncthreads covers the hazard)

    float e1r[16], e2r[32];

    // encoder
    stage<16,  32, 0, false>(Win, smem, 0, 0,   nullptr, nullptr, growCta, Ntot, tid); // x  -> ch0-31
    stage<32,  32, 0, true >(We1, smem, 0, 0,   e1r,     nullptr, growCta, Ntot, tid); // e1 -> ch0-31 + regs
    stage<32,  64, 0, true >(We2, smem, 0, 0,   e2r,     nullptr, growCta, Ntot, tid); // e2 -> ch0-63 + regs
    stage<64, 128, 0, false>(We3, smem, 0, 0,   nullptr, nullptr, growCta, Ntot, tid); // e3 -> ch0-127

    // decoder stage 3: cat3 = [e3 ch0-127 | lat3 ch128-255]
    stage<128,128, 0, false>(Wl3, smem, 0, 128, nullptr, nullptr, growCta, Ntot, tid); // lat3
    stage<256,128, 1, false>(Wm3, smem, 0, 0,   nullptr, nullptr, growCta, Ntot, tid); // t3 -> ch0-127
    stage<128, 64, 0, false>(Wu3, smem, 0, 0,   nullptr, nullptr, growCta, Ntot, tid); // x2 -> ch0-63

    // decoder stage 2: cat2 = [x2 ch0-63 | lat2 ch64-127]
    restage<64>(scr, 64, e2r, tid);                                                    // e2 -> ch64-127
    stage<64,  64, 0, false>(Wl2, smem, 64, 64, nullptr, nullptr, growCta, Ntot, tid); // lat2
    stage<128, 64, 1, false>(Wm2, smem, 0, 0,   nullptr, nullptr, growCta, Ntot, tid); // t2 -> ch0-63
    stage<64,  32, 0, false>(Wu2, smem, 0, 0,   nullptr, nullptr, growCta, Ntot, tid); // x1 -> ch0-31

    // decoder stage 1: cat1 = [x1 ch0-31 | lat1 ch32-63]
    restage<32>(scr, 32, e1r, tid);                                                    // e1 -> ch32-63
    stage<32,  32, 0, false>(Wl1, smem, 32, 32, nullptr, nullptr, growCta, Ntot, tid); // lat1
    stage<64,  32, 1, false>(Wm1, smem, 0, 0,   nullptr, nullptr, growCta, Ntot, tid); // t1 -> ch0-31

    // final upsample -> gmem [N, 32]
    stage<32,  32, 2, false>(Wu1, smem, 0, 0,   nullptr, out, growCta, Ntot, tid);
}

extern "C" void kernel_launch(void* const* d_in, const int* in_sizes, int n_in,
                              void* d_out, int out_size)
{
    const float* feat = (const float*)d_in[0];
    // d_in[1] = coords — sparse structure only; unused for 1x1 subm convs
    const float* Win = (const float*)d_in[2];
    const float* We1 = (const float*)d_in[3];
    const float* We2 = (const float*)d_in[4];
    const float* We3 = (const float*)d_in[5];
    const float* Wl1 = (const float*)d_in[6];
    const float* Wl2 = (const float*)d_in[7];
    const float* Wl3 = (const float*)d_in[8];
    const float* Wm1 = (const float*)d_in[9];
    const float* Wm2 = (const float*)d_in[10];
    const float* Wm3 = (const float*)d_in[11];
    const float* Wu1 = (const float*)d_in[12];
    const float* Wu2 = (const float*)d_in[13];
    const float* Wu3 = (const float*)d_in[14];

    const int N = in_sizes[0] / 16;

    cudaFuncSetAttribute(backbone_mma,
                         cudaFuncAttributeMaxDynamicSharedMemorySize, SMEM_BYTES);

    const int grid = (N + MROWS - 1) / MROWS;
    backbone_mma<<<grid, THREADS, SMEM_BYTES>>>(
        feat, Win, We1, We2, We3, Wl1, Wl2, Wl3,
        Wm1, Wm2, Wm3, Wu1, Wu2, Wu3, (float*)d_out, N);
}

// round 13
// speedup vs baseline: 1.0396x; 1.0396x over previous
#include <cuda_runtime.h>
#include <cstdint>

// Fused sparse-UNet backbone, round 13: 3xTF32 mma.sync.
// R12 with the ESAVE buffer overflow fixed (per-warp tile work is unchanged
// from R11 — 32 rows x N/2 cols — so e1r needs 16 floats, e2r 32).
// 256 thr / 128 rows per CTA (weight staging amortized) + warp tile 32xN/2
// (B-frags shared across 2 m16 tiles) -> 40 LDS vs 48 HMMA per warp-8k-slice.

#define THREADS 256
#define MROWS   128
#define PW      260                    // scratch pitch (floats), ==4 mod 32
#define KC      32                     // k-chunk
#define PNMAX   (128 + 8)
#define OFF_WHI 0
#define OFF_WLO (KC * PNMAX)           // 4352
#define OFF_SCR (2 * KC * PNMAX)       // 8704
#define SMEM_FLOATS (OFF_SCR + MROWS * PW)
#define SMEM_BYTES  (SMEM_FLOATS * 4)  // ~168 KB

__device__ __forceinline__ uint32_t tf32r(float x){
    uint32_t r; asm("cvt.rna.tf32.f32 %0, %1;" : "=r"(r) : "f"(x)); return r;
}
__device__ __forceinline__ float frelu(float v){ return v > 0.f ? v : 0.f; }

__device__ __forceinline__ void mma8(float* d, const uint32_t* a, const uint32_t* b){
    asm volatile("mma.sync.aligned.m16n8k8.row.col.f32.tf32.tf32.f32 "
        "{%0,%1,%2,%3},{%4,%5,%6,%7},{%8,%9},{%0,%1,%2,%3};"
        : "+f"(d[0]), "+f"(d[1]), "+f"(d[2]), "+f"(d[3])
        : "r"(a[0]), "r"(a[1]), "r"(a[2]), "r"(a[3]), "r"(b[0]), "r"(b[1]));
}

// Warp (rg, cgh): rows [rg*32, +32) as 2 m16 tiles, cols [cgh*N/2, +N/2).
// EPI: 0 -> scratch ; 1 -> +pairsum(cat) -> scratch ; 2 -> gmem [*,32].
template<int K, int N, int EPI, bool ESAVE>
__device__ __forceinline__ void stage(const float* __restrict__ Wg,
                                      float* __restrict__ smem,
                                      int aBase, int dBase,
                                      float* __restrict__ eSave,
                                      float* __restrict__ gout,
                                      int growCta, int Ntot, int tid)
{
    constexpr int PN  = N + 8;               // weight pitch, ==8 mod 32
    constexpr int Nw  = N / 2;               // cols per warp
    constexpr int NTw = Nw / 8;              // n8-tiles per warp
    constexpr int KcC = (K < KC) ? K : KC;
    constexpr int NCH = K / KcC;
    const int lane = tid & 31;
    const int warp = tid >> 5;
    const int rg   = warp >> 1;              // row group 0..3
    const int cgh  = warp & 1;               // col half 0..1
    const int rbase = rg * 32;
    const int qr = lane >> 2, qc = lane & 3;
    float* scr = smem + OFF_SCR;

    float acc[2][NTw][4];
#pragma unroll
    for (int t = 0; t < 2; t++)
#pragma unroll
        for (int j = 0; j < NTw; j++){ acc[t][j][0]=acc[t][j][1]=acc[t][j][2]=acc[t][j][3]=0.f; }

    for (int ch = 0; ch < NCH; ch++){
        const int k0 = ch * KcC;
        __syncthreads();                     // weight buf free / prev stores visible
        {
            const float* wsrc = Wg + (size_t)k0 * N;
            for (int i = tid; i < KcC * N; i += THREADS){
                const int k = i / N, n = i % N;       // N pow2 -> shifts
                float w = wsrc[i];
                float hv = __uint_as_float(tf32r(w));
                smem[OFF_WHI + k * PN + n] = hv;
                smem[OFF_WLO + k * PN + n] = __uint_as_float(tf32r(w - hv));
            }
        }
        __syncthreads();

#pragma unroll
        for (int s = 0; s < KcC / 8; s++){
            const int kcol = aBase + k0 + 8 * s + qc;
            uint32_t ah[2][4], al[2][4];
#pragma unroll
            for (int t = 0; t < 2; t++){
                const float* rp = scr + (rbase + t * 16 + qr) * PW + kcol;
                float a0 = rp[0], a1 = rp[8 * PW], a2 = rp[4], a3 = rp[8 * PW + 4];
                ah[t][0] = tf32r(a0); ah[t][1] = tf32r(a1);
                ah[t][2] = tf32r(a2); ah[t][3] = tf32r(a3);
                al[t][0] = tf32r(a0 - __uint_as_float(ah[t][0]));
                al[t][1] = tf32r(a1 - __uint_as_float(ah[t][1]));
                al[t][2] = tf32r(a2 - __uint_as_float(ah[t][2]));
                al[t][3] = tf32r(a3 - __uint_as_float(ah[t][3]));
            }
            const float* bh = smem + OFF_WHI + (8 * s + qc) * PN + cgh * Nw + qr;
            const float* bl = smem + OFF_WLO + (8 * s + qc) * PN + cgh * Nw + qr;
#pragma unroll
            for (int j = 0; j < NTw; j++){
                uint32_t bhi[2] = { __float_as_uint(bh[8 * j]),
                                    __float_as_uint(bh[4 * PN + 8 * j]) };
                uint32_t blo[2] = { __float_as_uint(bl[8 * j]),
                                    __float_as_uint(bl[4 * PN + 8 * j]) };
                mma8(acc[0][j], ah[0], bhi);
                mma8(acc[0][j], ah[0], blo);
                mma8(acc[0][j], al[0], bhi);
                mma8(acc[1][j], ah[1], bhi);
                mma8(acc[1][j], ah[1], blo);
                mma8(acc[1][j], al[1], bhi);
            }
        }
    }

    // phase 1: relu (+red) into acc; all scratch READS happen here
#pragma unroll
    for (int t = 0; t < 2; t++)
#pragma unroll
        for (int j = 0; j < NTw; j++){
            float v0 = frelu(acc[t][j][0]), v1 = frelu(acc[t][j][1]);
            float v2 = frelu(acc[t][j][2]), v3 = frelu(acc[t][j][3]);
            if constexpr (EPI == 1){
                const int cc = aBase + 2 * cgh * Nw + 16 * j + 4 * qc;
                const float4 qa = *(const float4*)&scr[(rbase + t*16 + qr) * PW + cc];
                const float4 qb = *(const float4*)&scr[(rbase + t*16 + qr + 8) * PW + cc];
                v0 += qa.x + qa.y;  v1 += qa.z + qa.w;
                v2 += qb.x + qb.y;  v3 += qb.z + qb.w;
            }
            if constexpr (ESAVE){
                float* e = eSave + (t * NTw + j) * 4;
                e[0] = v0; e[1] = v1; e[2] = v2; e[3] = v3;
            }
            acc[t][j][0] = v0; acc[t][j][1] = v1; acc[t][j][2] = v2; acc[t][j][3] = v3;
        }

    if constexpr (EPI == 2){
#pragma unroll
        for (int t = 0; t < 2; t++)
#pragma unroll
            for (int j = 0; j < NTw; j++){
                const int col = cgh * Nw + 8 * j + 2 * qc;
                const int g0 = growCta + rbase + t * 16 + qr;
                if (g0 < Ntot)
                    *(float2*)&gout[(size_t)g0 * 32 + col] = make_float2(acc[t][j][0], acc[t][j][1]);
                if (g0 + 8 < Ntot)
                    *(float2*)&gout[(size_t)(g0 + 8) * 32 + col] = make_float2(acc[t][j][2], acc[t][j][3]);
            }
        return;
    }

    __syncthreads();                         // all reads done -> safe to overwrite
#pragma unroll
    for (int t = 0; t < 2; t++)
#pragma unroll
        for (int j = 0; j < NTw; j++){
            const int col = dBase + cgh * Nw + 8 * j + 2 * qc;
            *(float2*)&scr[(rbase + t*16 + qr) * PW + col]     = make_float2(acc[t][j][0], acc[t][j][1]);
            *(float2*)&scr[(rbase + t*16 + qr + 8) * PW + col] = make_float2(acc[t][j][2], acc[t][j][3]);
        }
}

// write saved e-regs back to scratch at channel base (same mapping as stores)
template<int N>
__device__ __forceinline__ void restage(float* __restrict__ scr, int base,
                                        const float* __restrict__ e, int tid){
    constexpr int Nw = N / 2, NTw = Nw / 8;
    const int lane = tid & 31, warp = tid >> 5;
    const int rg = warp >> 1, cgh = warp & 1;
    const int rbase = rg * 32;
    const int qr = lane >> 2, qc = lane & 3;
#pragma unroll
    for (int t = 0; t < 2; t++)
#pragma unroll
        for (int j = 0; j < NTw; j++){
            const float* ep = e + (t * NTw + j) * 4;
            const int col = base + cgh * Nw + 8 * j + 2 * qc;
            *(float2*)&scr[(rbase + t*16 + qr) * PW + col]     = make_float2(ep[0], ep[1]);
            *(float2*)&scr[(rbase + t*16 + qr + 8) * PW + col] = make_float2(ep[2], ep[3]);
        }
}

__global__ void __launch_bounds__(THREADS, 1)
backbone_mma(const float* __restrict__ feat,
             const float* __restrict__ Win,
             const float* __restrict__ We1, const float* __restrict__ We2,
             const float* __restrict__ We3,
             const float* __restrict__ Wl1, const float* __restrict__ Wl2,
             const float* __restrict__ Wl3,
             const float* __restrict__ Wm1, const float* __restrict__ Wm2,
             const float* __restrict__ Wm3,
             const float* __restrict__ Wu1, const float* __restrict__ Wu2,
             const float* __restrict__ Wu3,
             float* __restrict__ out, int Ntot)
{
    extern __shared__ float smem[];
    float* scr = smem + OFF_SCR;
    const int tid = threadIdx.x;
    const int growCta = blockIdx.x * MROWS;

    // feat[128 rows, 16 ch] -> scratch ch0-15
    {
        const int r = tid >> 1, h = tid & 1;
        const int g = growCta + r;
        float4 f0 = make_float4(0,0,0,0), f1 = f0;
        if (g < Ntot){
            const float4* src = (const float4*)&feat[(size_t)g * 16 + h * 8];
            f0 = src[0]; f1 = src[1];
        }
        *(float4*)&scr[r * PW + h * 8]     = f0;
        *(float4*)&scr[r * PW + h * 8 + 4] = f1;
    }
    // (first stage's leading __syncthreads covers the hazard)

    float e1r[16], e2r[32];   // per-warp tile: N=32 -> 16 floats, N=64 -> 32 floats

    // encoder
    stage<16,  32, 0, false>(Win, smem, 0, 0,   nullptr, nullptr, growCta, Ntot, tid); // x  -> ch0-31
    stage<32,  32, 0, true >(We1, smem, 0, 0,   e1r,     nullptr, growCta, Ntot, tid); // e1 -> ch0-31 + regs
    stage<32,  64, 0, true >(We2, smem, 0, 0,   e2r,     nullptr, growCta, Ntot, tid); // e2 -> ch0-63 + regs
    stage<64, 128, 0, false>(We3, smem, 0, 0,   nullptr, nullptr, growCta, Ntot, tid); // e3 -> ch0-127

    // decoder stage 3: cat3 = [e3 ch0-127 | lat3 ch128-255]
    stage<128,128, 0, false>(Wl3, smem, 0, 128, nullptr, nullptr, growCta, Ntot, tid); // lat3
    stage<256,128, 1, false>(Wm3, smem, 0, 0,   nullptr, nullptr, growCta, Ntot, tid); // t3 -> ch0-127
    stage<128, 64, 0, false>(Wu3, smem, 0, 0,   nullptr, nullptr, growCta, Ntot, tid); // x2 -> ch0-63

    // decoder stage 2: cat2 = [x2 ch0-63 | lat2 ch64-127]
    restage<64>(scr, 64, e2r, tid);                                                    // e2 -> ch64-127
    stage<64,  64, 0, false>(Wl2, smem, 64, 64, nullptr, nullptr, growCta, Ntot, tid); // lat2
    stage<128, 64, 1, false>(Wm2, smem, 0, 0,   nullptr, nullptr, growCta, Ntot, tid); // t2 -> ch0-63
    stage<64,  32, 0, false>(Wu2, smem, 0, 0,   nullptr, nullptr, growCta, Ntot, tid); // x1 -> ch0-31

    // decoder stage 1: cat1 = [x1 ch0-31 | lat1 ch32-63]
    restage<32>(scr, 32, e1r, tid);                                                    // e1 -> ch32-63
    stage<32,  32, 0, false>(Wl1, smem, 32, 32, nullptr, nullptr, growCta, Ntot, tid); // lat1
    stage<64,  32, 1, false>(Wm1, smem, 0, 0,   nullptr, nullptr, growCta, Ntot, tid); // t1 -> ch0-31

    // final upsample -> gmem [N, 32]
    stage<32,  32, 2, false>(Wu1, smem, 0, 0,   nullptr, out, growCta, Ntot, tid);
}

extern "C" void kernel_launch(void* const* d_in, const int* in_sizes, int n_in,
                              void* d_out, int out_size)
{
    const float* feat = (const float*)d_in[0];
    // d_in[1] = coords — sparse structure only; unused for 1x1 subm convs
    const float* Win = (const float*)d_in[2];
    const float* We1 = (const float*)d_in[3];
    const float* We2 = (const float*)d_in[4];
    const float* We3 = (const float*)d_in[5];
    const float* Wl1 = (const float*)d_in[6];
    const float* Wl2 = (const float*)d_in[7];
    const float* Wl3 = (const float*)d_in[8];
    const float* Wm1 = (const float*)d_in[9];
    const float* Wm2 = (const float*)d_in[10];
    const float* Wm3 = (const float*)d_in[11];
    const float* Wu1 = (const float*)d_in[12];
    const float* Wu2 = (const float*)d_in[13];
    const float* Wu3 = (const float*)d_in[14];

    const int N = in_sizes[0] / 16;

    cudaFuncSetAttribute(backbone_mma,
                         cudaFuncAttributeMaxDynamicSharedMemorySize, SMEM_BYTES);

    const int grid = (N + MROWS - 1) / MROWS;
    backbone_mma<<<grid, THREADS, SMEM_BYTES>>>(
        feat, Win, We1, We2, We3, Wl1, Wl2, Wl3,
        Wm1, Wm2, Wm3, Wu1, Wu2, Wu3, (float*)d_out, N);
}

// round 14
// speedup vs baseline: 1.4089x; 1.3553x over previous
#include <cuda_runtime.h>
#include <cstdint>

// Round 14: 3xTF32 mma.sync + weight pre-conversion + cp.async double buffer.
// A pre-pass kernel converts all weights ONCE to tf32 hi/lo in staged padded
// layout (g_whi/g_wlo). The main kernel streams each 32-k chunk with cp.async
// into a double buffer, overlapping the next chunk's copy with this chunk's
// MMA loop; one barrier per chunk. Warp tile 32 rows x N/2 cols (R13 geometry).

#define THREADS 256
#define MROWS   128
#define PW      260                    // scratch pitch, ==4 mod 32
#define KC      32
// WBUF: 2 bufs x (hi+lo) x KC*PNMAX floats ; PNMAX=136
#define BUFHALF 4352                   // KC*136 floats
#define BUFSTR  (2 * BUFHALF)          // one buffer (hi+lo)
#define OFF_SCRF (2 * BUFSTR)          // 17408 floats
#define SMEM_FLOATS (OFF_SCRF + MROWS * PW)
#define SMEM_BYTES  (SMEM_FLOATS * 4)  // 202752 B

// staged weight arrays (floats), per-stage offsets (K x (N+8) each)
#define TOTW 95872
__device__ float g_whi[TOTW];
__device__ float g_wlo[TOTW];

__device__ __forceinline__ uint32_t tf32r(float x){
    uint32_t r; asm("cvt.rna.tf32.f32 %0, %1;" : "=r"(r) : "f"(x)); return r;
}
__device__ __forceinline__ float frelu(float v){ return v > 0.f ? v : 0.f; }
__device__ __forceinline__ uint32_t smem_u32(const void* p){
    uint32_t a;
    asm("{ .reg .u64 t; cvta.to.shared.u64 t, %1; cvt.u32.u64 %0, t; }" : "=r"(a) : "l"(p));
    return a;
}
__device__ __forceinline__ void cpa16(uint32_t s, const float* g){
    asm volatile("cp.async.cg.shared.global [%0], [%1], 16;" :: "r"(s), "l"(g));
}
#define CPA_COMMIT() asm volatile("cp.async.commit_group;" ::: "memory")
#define CPA_WAIT0()  asm volatile("cp.async.wait_group 0;" ::: "memory")

__device__ __forceinline__ void mma8(float* d, const uint32_t* a, const uint32_t* b){
    asm volatile("mma.sync.aligned.m16n8k8.row.col.f32.tf32.tf32.f32 "
        "{%0,%1,%2,%3},{%4,%5,%6,%7},{%8,%9},{%0,%1,%2,%3};"
        : "+f"(d[0]), "+f"(d[1]), "+f"(d[2]), "+f"(d[3])
        : "r"(a[0]), "r"(a[1]), "r"(a[2]), "r"(a[3]), "r"(b[0]), "r"(b[1]));
}

// ---------------- pre-pass: convert all weights to hi/lo staged layout -------
__global__ void prep_weights(const float* __restrict__ Win,
                             const float* __restrict__ We1, const float* __restrict__ We2,
                             const float* __restrict__ We3,
                             const float* __restrict__ Wl1, const float* __restrict__ Wl2,
                             const float* __restrict__ Wl3,
                             const float* __restrict__ Wm1, const float* __restrict__ Wm2,
                             const float* __restrict__ Wm3,
                             const float* __restrict__ Wu1, const float* __restrict__ Wu2,
                             const float* __restrict__ Wu3)
{
    const float* Ws[13] = {Win, We1, We2, We3, Wl3, Wm3, Wu3, Wl2, Wm2, Wu2, Wl1, Wm1, Wu1};
    const int   Ks[13]  = {16, 32, 32, 64, 128, 256, 128, 64, 128, 64, 32, 64, 32};
    const int   NsA[13] = {32, 32, 64, 128, 128, 128, 64, 64, 64, 32, 32, 32, 32};
    const int   Os[13]  = {0, 640, 1920, 4224, 12928, 30336, 65152, 74368, 78976, 88192,
                           90752, 92032, 94592};
    const int gt = blockIdx.x * blockDim.x + threadIdx.x;
    const int gs = gridDim.x * blockDim.x;
#pragma unroll 1
    for (int s = 0; s < 13; s++){
        const int K = Ks[s], N = NsA[s], PN = N + 8, off = Os[s];
        const float* W = Ws[s];
        for (int i = gt; i < K * N; i += gs){
            const int k = i / N, n = i - (i / N) * N;
            float w = W[i];
            float hi = __uint_as_float(tf32r(w));
            g_whi[off + k * PN + n] = hi;
            g_wlo[off + k * PN + n] = __uint_as_float(tf32r(w - hi));
        }
    }
}

// ---------------- main stage -------------------------------------------------
// Warp (rg,cgh): rows [rg*32,+32) as 2 m16 tiles, cols [cgh*N/2,+N/2).
// EPI: 0 -> scratch ; 1 -> +pairsum(cat) -> scratch ; 2 -> gmem [*,32].
template<int K, int N, int EPI, bool ESAVE>
__device__ __forceinline__ void stage(int woff,
                                      float* __restrict__ smem, uint32_t sb32,
                                      int aBase, int dBase,
                                      float* __restrict__ eSave,
                                      float* __restrict__ gout,
                                      int growCta, int Ntot, int tid)
{
    constexpr int PN  = N + 8;
    constexpr int Nw  = N / 2;
    constexpr int NTw = Nw / 8;
    constexpr int KcC = (K < KC) ? K : KC;
    constexpr int NCH = K / KcC;
    constexpr int CHF = KcC * PN;            // floats per chunk (div by 8)
    const int lane = tid & 31;
    const int warp = tid >> 5;
    const int rg   = warp >> 1;
    const int cgh  = warp & 1;
    const int rbase = rg * 32;
    const int qr = lane >> 2, qc = lane & 3;
    float* scr = smem + OFF_SCRF;

    float acc[2][NTw][4];
#pragma unroll
    for (int t = 0; t < 2; t++)
#pragma unroll
        for (int j = 0; j < NTw; j++){ acc[t][j][0]=acc[t][j][1]=acc[t][j][2]=acc[t][j][3]=0.f; }

    // issue chunk 0 into buffer 0 (safe: prior stage's epilogue barrier passed)
    {
        const float* gh = g_whi + woff;
        const float* gl = g_wlo + woff;
        for (int i = tid * 4; i < CHF; i += THREADS * 4){
            cpa16(sb32 + i * 4, gh + i);
            cpa16(sb32 + BUFHALF * 4 + i * 4, gl + i);
        }
        CPA_COMMIT();
    }

    for (int ch = 0; ch < NCH; ch++){
        const int b = ch & 1;
        CPA_WAIT0();                          // chunk ch landed
        __syncthreads();                      // visible to all; prev kloop done
        if (ch + 1 < NCH){                    // stream next chunk during MMA
            const int nb = (ch + 1) & 1;
            const float* gh = g_whi + woff + (ch + 1) * CHF;
            const float* gl = g_wlo + woff + (ch + 1) * CHF;
            const uint32_t sh = sb32 + nb * (BUFSTR * 4);
            for (int i = tid * 4; i < CHF; i += THREADS * 4){
                cpa16(sh + i * 4, gh + i);
                cpa16(sh + BUFHALF * 4 + i * 4, gl + i);
            }
            CPA_COMMIT();
        }

        const float* bufp = smem + b * BUFSTR;
        const int k0 = ch * KcC;
#pragma unroll
        for (int s = 0; s < KcC / 8; s++){
            const int kcol = aBase + k0 + 8 * s + qc;
            uint32_t ah[2][4], al[2][4];
#pragma unroll
            for (int t = 0; t < 2; t++){
                const float* rp = scr + (rbase + t * 16 + qr) * PW + kcol;
                float a0 = rp[0], a1 = rp[8 * PW], a2 = rp[4], a3 = rp[8 * PW + 4];
                ah[t][0] = tf32r(a0); ah[t][1] = tf32r(a1);
                ah[t][2] = tf32r(a2); ah[t][3] = tf32r(a3);
                al[t][0] = tf32r(a0 - __uint_as_float(ah[t][0]));
                al[t][1] = tf32r(a1 - __uint_as_float(ah[t][1]));
                al[t][2] = tf32r(a2 - __uint_as_float(ah[t][2]));
                al[t][3] = tf32r(a3 - __uint_as_float(ah[t][3]));
            }
            const float* bh = bufp + (8 * s + qc) * PN + cgh * Nw + qr;
            const float* bl = bh + BUFHALF;
#pragma unroll
            for (int j = 0; j < NTw; j++){
                uint32_t bhi[2] = { __float_as_uint(bh[8 * j]),
                                    __float_as_uint(bh[4 * PN + 8 * j]) };
                uint32_t blo[2] = { __float_as_uint(bl[8 * j]),
                                    __float_as_uint(bl[4 * PN + 8 * j]) };
                mma8(acc[0][j], ah[0], bhi);
                mma8(acc[0][j], ah[0], blo);
                mma8(acc[0][j], al[0], bhi);
                mma8(acc[1][j], ah[1], bhi);
                mma8(acc[1][j], ah[1], blo);
                mma8(acc[1][j], al[1], bhi);
            }
        }
    }

    // phase 1: relu (+red) into acc; all scratch READS happen here
#pragma unroll
    for (int t = 0; t < 2; t++)
#pragma unroll
        for (int j = 0; j < NTw; j++){
            float v0 = frelu(acc[t][j][0]), v1 = frelu(acc[t][j][1]);
            float v2 = frelu(acc[t][j][2]), v3 = frelu(acc[t][j][3]);
            if constexpr (EPI == 1){
                const int cc = aBase + 2 * cgh * Nw + 16 * j + 4 * qc;
                const float4 qa = *(const float4*)&scr[(rbase + t*16 + qr) * PW + cc];
                const float4 qb = *(const float4*)&scr[(rbase + t*16 + qr + 8) * PW + cc];
                v0 += qa.x + qa.y;  v1 += qa.z + qa.w;
                v2 += qb.x + qb.y;  v3 += qb.z + qb.w;
            }
            if constexpr (ESAVE){
                float* e = eSave + (t * NTw + j) * 4;
                e[0] = v0; e[1] = v1; e[2] = v2; e[3] = v3;
            }
            acc[t][j][0] = v0; acc[t][j][1] = v1; acc[t][j][2] = v2; acc[t][j][3] = v3;
        }

    if constexpr (EPI == 2){
#pragma unroll
        for (int t = 0; t < 2; t++)
#pragma unroll
            for (int j = 0; j < NTw; j++){
                const int col = cgh * Nw + 8 * j + 2 * qc;
                const int g0 = growCta + rbase + t * 16 + qr;
                if (g0 < Ntot)
                    *(float2*)&gout[(size_t)g0 * 32 + col] = make_float2(acc[t][j][0], acc[t][j][1]);
                if (g0 + 8 < Ntot)
                    *(float2*)&gout[(size_t)(g0 + 8) * 32 + col] = make_float2(acc[t][j][2], acc[t][j][3]);
            }
        return;
    }

    __syncthreads();                          // all reads done -> safe to overwrite
#pragma unroll
    for (int t = 0; t < 2; t++)
#pragma unroll
        for (int j = 0; j < NTw; j++){
            const int col = dBase + cgh * Nw + 8 * j + 2 * qc;
            *(float2*)&scr[(rbase + t*16 + qr) * PW + col]     = make_float2(acc[t][j][0], acc[t][j][1]);
            *(float2*)&scr[(rbase + t*16 + qr + 8) * PW + col] = make_float2(acc[t][j][2], acc[t][j][3]);
        }
}

template<int N>
__device__ __forceinline__ void restage(float* __restrict__ scr, int base,
                                        const float* __restrict__ e, int tid){
    constexpr int Nw = N / 2, NTw = Nw / 8;
    const int lane = tid & 31, warp = tid >> 5;
    const int rg = warp >> 1, cgh = warp & 1;
    const int rbase = rg * 32;
    const int qr = lane >> 2, qc = lane & 3;
#pragma unroll
    for (int t = 0; t < 2; t++)
#pragma unroll
        for (int j = 0; j < NTw; j++){
            const float* ep = e + (t * NTw + j) * 4;
            const int col = base + cgh * Nw + 8 * j + 2 * qc;
            *(float2*)&scr[(rbase + t*16 + qr) * PW + col]     = make_float2(ep[0], ep[1]);
            *(float2*)&scr[(rbase + t*16 + qr + 8) * PW + col] = make_float2(ep[2], ep[3]);
        }
}

__global__ void __launch_bounds__(THREADS, 1)
backbone_mma(const float* __restrict__ feat, float* __restrict__ out, int Ntot)
{
    extern __shared__ float smem[];
    float* scr = smem + OFF_SCRF;
    const int tid = threadIdx.x;
    const int growCta = blockIdx.x * MROWS;
    const uint32_t sb32 = smem_u32(smem);

    // feat[128 rows, 16 ch] -> scratch ch0-15
    {
        const int r = tid >> 1, h = tid & 1;
        const int g = growCta + r;
        float4 f0 = make_float4(0,0,0,0), f1 = f0;
        if (g < Ntot){
            const float4* src = (const float4*)&feat[(size_t)g * 16 + h * 8];
            f0 = src[0]; f1 = src[1];
        }
        *(float4*)&scr[r * PW + h * 8]     = f0;
        *(float4*)&scr[r * PW + h * 8 + 4] = f1;
    }

    float e1r[16], e2r[32];

    // encoder
    stage<16,  32, 0, false>(0,     smem, sb32, 0, 0,   nullptr, nullptr, growCta, Ntot, tid);
    stage<32,  32, 0, true >(640,   smem, sb32, 0, 0,   e1r,     nullptr, growCta, Ntot, tid);
    stage<32,  64, 0, true >(1920,  smem, sb32, 0, 0,   e2r,     nullptr, growCta, Ntot, tid);
    stage<64, 128, 0, false>(4224,  smem, sb32, 0, 0,   nullptr, nullptr, growCta, Ntot, tid);

    // decoder stage 3: cat3 = [e3 ch0-127 | lat3 ch128-255]
    stage<128,128, 0, false>(12928, smem, sb32, 0, 128, nullptr, nullptr, growCta, Ntot, tid);
    stage<256,128, 1, false>(30336, smem, sb32, 0, 0,   nullptr, nullptr, growCta, Ntot, tid);
    stage<128, 64, 0, false>(65152, smem, sb32, 0, 0,   nullptr, nullptr, growCta, Ntot, tid);

    // decoder stage 2: cat2 = [x2 ch0-63 | lat2 ch64-127]
    restage<64>(scr, 64, e2r, tid);
    stage<64,  64, 0, false>(74368, smem, sb32, 64, 64, nullptr, nullptr, growCta, Ntot, tid);
    stage<128, 64, 1, false>(78976, smem, sb32, 0, 0,   nullptr, nullptr, growCta, Ntot, tid);
    stage<64,  32, 0, false>(88192, smem, sb32, 0, 0,   nullptr, nullptr, growCta, Ntot, tid);

    // decoder stage 1: cat1 = [x1 ch0-31 | lat1 ch32-63]
    restage<32>(scr, 32, e1r, tid);
    stage<32,  32, 0, false>(90752, smem, sb32, 32, 32, nullptr, nullptr, growCta, Ntot, tid);
    stage<64,  32, 1, false>(92032, smem, sb32, 0, 0,   nullptr, nullptr, growCta, Ntot, tid);

    // final upsample -> gmem [N, 32]
    stage<32,  32, 2, false>(94592, smem, sb32, 0, 0,   nullptr, out, growCta, Ntot, tid);
}

extern "C" void kernel_launch(void* const* d_in, const int* in_sizes, int n_in,
                              void* d_out, int out_size)
{
    const float* feat = (const float*)d_in[0];
    // d_in[1] = coords — sparse structure only; unused for 1x1 subm convs
    const float* Win = (const float*)d_in[2];
    const float* We1 = (const float*)d_in[3];
    const float* We2 = (const float*)d_in[4];
    const float* We3 = (const float*)d_in[5];
    const float* Wl1 = (const float*)d_in[6];
    const float* Wl2 = (const float*)d_in[7];
    const float* Wl3 = (const float*)d_in[8];
    const float* Wm1 = (const float*)d_in[9];
    const float* Wm2 = (const float*)d_in[10];
    const float* Wm3 = (const float*)d_in[11];
    const float* Wu1 = (const float*)d_in[12];
    const float* Wu2 = (const float*)d_in[13];
    const float* Wu3 = (const float*)d_in[14];

    const int N = in_sizes[0] / 16;

    prep_weights<<<232, 256>>>(Win, We1, We2, We3, Wl1, Wl2, Wl3,
                               Wm1, Wm2, Wm3, Wu1, Wu2, Wu3);

    cudaFuncSetAttribute(backbone_mma,
                         cudaFuncAttributeMaxDynamicSharedMemorySize, SMEM_BYTES);
    const int grid = (N + MROWS - 1) / MROWS;
    backbone_mma<<<grid, THREADS, SMEM_BYTES>>>(feat, (float*)d_out, N);
}

// round 15
// speedup vs baseline: 1.4403x; 1.0222x over previous
#include <cuda_runtime.h>
#include <cstdint>

// Round 15: 3xTF32 mma.sync. vs R14:
//  - A fragments via ldmatrix.m8n8.x4 (2 instrs/slice instead of 8 scalar LDS)
//  - B fragments pre-packed per-(slice,colhalf,lane) by the prep kernel with a
//    padded lane stride (==4 mod 8 floats) -> conflict-free float4 loads
//    (NTw loads/slice instead of 4*NTw scalar LDS)
//  - same double-buffered cp.async streaming + barrier structure as R14.

#define THREADS 256
#define MROWS   128
#define PW      260                    // scratch pitch, ==4 mod 32 (ldmatrix conflict-free)
#define KC      32
#define MAXCHF  5120                   // max per-plane chunk floats (N=128: 4*64*20)
#define BUFTOT  (2 * MAXCHF)           // one buffer: hi + lo
#define OFF_SCRF (2 * BUFTOT)          // 20480 floats
#define SMEM_FLOATS (OFF_SCRF + MROWS * PW)
#define SMEM_BYTES  (SMEM_FLOATS * 4)  // 215040 B

#define TOTB 128512
__device__ float g_bhi[TOTB];
__device__ float g_blo[TOTB];

__device__ __forceinline__ uint32_t tf32r(float x){
    uint32_t r; asm("cvt.rna.tf32.f32 %0, %1;" : "=r"(r) : "f"(x)); return r;
}
__device__ __forceinline__ float frelu(float v){ return v > 0.f ? v : 0.f; }
__device__ __forceinline__ uint32_t smem_u32(const void* p){
    uint32_t a;
    asm("{ .reg .u64 t; cvta.to.shared.u64 t, %1; cvt.u32.u64 %0, t; }" : "=r"(a) : "l"(p));
    return a;
}
__device__ __forceinline__ void cpa16(uint32_t s, const float* g){
    asm volatile("cp.async.cg.shared.global [%0], [%1], 16;" :: "r"(s), "l"(g));
}
#define CPA_COMMIT() asm volatile("cp.async.commit_group;" ::: "memory")
#define CPA_WAIT0()  asm volatile("cp.async.wait_group 0;" ::: "memory")

__device__ __forceinline__ void ldm4(uint32_t* r, uint32_t addr){
    asm volatile("ldmatrix.sync.aligned.m8n8.x4.shared.b16 {%0,%1,%2,%3}, [%4];"
        : "=r"(r[0]), "=r"(r[1]), "=r"(r[2]), "=r"(r[3]) : "r"(addr));
}
__device__ __forceinline__ void mma8(float* d, const uint32_t* a, const uint32_t* b){
    asm volatile("mma.sync.aligned.m16n8k8.row.col.f32.tf32.tf32.f32 "
        "{%0,%1,%2,%3},{%4,%5,%6,%7},{%8,%9},{%0,%1,%2,%3};"
        : "+f"(d[0]), "+f"(d[1]), "+f"(d[2]), "+f"(d[3])
        : "r"(a[0]), "r"(a[1]), "r"(a[2]), "r"(a[3]), "r"(b[0]), "r"(b[1]));
}

// -------- prep: pack B fragments per (slice, colhalf, lane) as tf32 hi/lo ----
__global__ void prep_weights(const float* __restrict__ Win,
                             const float* __restrict__ We1, const float* __restrict__ We2,
                             const float* __restrict__ We3,
                             const float* __restrict__ Wl1, const float* __restrict__ Wl2,
                             const float* __restrict__ Wl3,
                             const float* __restrict__ Wm1, const float* __restrict__ Wm2,
                             const float* __restrict__ Wm3,
                             const float* __restrict__ Wu1, const float* __restrict__ Wu2,
                             const float* __restrict__ Wu3)
{
    const float* Ws[13] = {Win, We1, We2, We3, Wl3, Wm3, Wu3, Wl2, Wm2, Wu2, Wl1, Wm1, Wu1};
    const int   Ks[13]  = {16, 32, 32, 64, 128, 256, 128, 64, 128, 64, 32, 64, 32};
    const int   Ns[13]  = {32, 32, 64, 128, 128, 128, 64, 64, 64, 32, 32, 32, 32};
    const int   Os[13]  = {0, 1536, 4608, 7680, 17920, 38400, 79360, 91648, 97792,
                           110080, 116224, 119296, 125440};
    const int gt = blockIdx.x * blockDim.x + threadIdx.x;
    const int gs = gridDim.x * blockDim.x;
#pragma unroll 1
    for (int st = 0; st < 13; st++){
        const int K = Ks[st], N = Ns[st], off = Os[st];
        const int NTw = N / 16;
        const int STRIDE = (NTw == 8) ? 20 : 12;
        const int total = (K / 8) * 64 * STRIDE;
        const float* W = Ws[st];
        for (int e = gt; e < total; e += gs){
            const int b = e / STRIDE, r = e - (e / STRIDE) * STRIDE;
            float hv = 0.f, lv = 0.f;
            if (r < 2 * NTw){
                const int j = r >> 1, p = r & 1;
                const int lane = b & 31, cg = (b >> 5) & 1, s = b >> 6;
                const int qr = lane >> 2, qc = lane & 3;
                const int k = 8 * s + qc + 4 * p;
                const int n = cg * (N / 2) + 8 * j + qr;
                float w = W[k * N + n];
                hv = __uint_as_float(tf32r(w));
                lv = __uint_as_float(tf32r(w - hv));
            }
            g_bhi[off + e] = hv;
            g_blo[off + e] = lv;
        }
    }
}

// -------- main stage ---------------------------------------------------------
// Warp (rg,cgh): rows [rg*32,+32) as 2 m16 tiles, cols [cgh*N/2,+N/2).
// EPI: 0 -> scratch ; 1 -> +pairsum(cat) -> scratch ; 2 -> gmem [*,32].
template<int K, int N, int EPI, bool ESAVE>
__device__ __forceinline__ void stage(int woff,
                                      float* __restrict__ smem, uint32_t sb32,
                                      int aBase, int dBase,
                                      float* __restrict__ eSave,
                                      float* __restrict__ gout,
                                      int growCta, int Ntot, int tid)
{
    constexpr int Nw  = N / 2;
    constexpr int NTw = N / 16;
    constexpr int STRIDE = (NTw == 8) ? 20 : 12;
    constexpr int KcC = (K < KC) ? K : KC;
    constexpr int NCH = K / KcC;
    constexpr int SLC = KcC / 8;                 // slices per chunk
    constexpr int CHF = SLC * 64 * STRIDE;       // per-plane chunk floats
    const int lane = tid & 31;
    const int warp = tid >> 5;
    const int rg   = warp >> 1;
    const int cgh  = warp & 1;
    const int rbase = rg * 32;
    const int qr = lane >> 2, qc = lane & 3;
    float* scr = smem + OFF_SCRF;

    // per-thread ldmatrix base address (row/colsel from lane)
    const int rowA   = (lane & 7) + ((lane >> 3) & 1) * 8;
    const int colSel = (lane >> 4) & 1;
    const uint32_t aB32 = sb32 + (uint32_t)(OFF_SCRF + (rbase + rowA) * PW
                                            + aBase + 4 * colSel) * 4u;

    float acc[2][NTw][4];
#pragma unroll
    for (int t = 0; t < 2; t++)
#pragma unroll
        for (int j = 0; j < NTw; j++){ acc[t][j][0]=acc[t][j][1]=acc[t][j][2]=acc[t][j][3]=0.f; }

    // issue chunk 0 into buffer 0
    {
        const float* gh = g_bhi + woff;
        const float* gl = g_blo + woff;
        for (int i = tid * 4; i < CHF; i += THREADS * 4){
            cpa16(sb32 + i * 4, gh + i);
            cpa16(sb32 + (CHF + i) * 4, gl + i);
        }
        CPA_COMMIT();
    }

    for (int ch = 0; ch < NCH; ch++){
        const int b = ch & 1;
        CPA_WAIT0();
        __syncthreads();
        if (ch + 1 < NCH){
            const int nb = (ch + 1) & 1;
            const float* gh = g_bhi + woff + (ch + 1) * CHF;
            const float* gl = g_blo + woff + (ch + 1) * CHF;
            const uint32_t sh = sb32 + (uint32_t)nb * (BUFTOT * 4);
            for (int i = tid * 4; i < CHF; i += THREADS * 4){
                cpa16(sh + i * 4, gh + i);
                cpa16(sh + (CHF + i) * 4, gl + i);
            }
            CPA_COMMIT();
        }

        const float* bufp = smem + b * BUFTOT;
        const int k0 = ch * KcC;
#pragma unroll
        for (int s = 0; s < SLC; s++){
            // A fragments: 2x ldmatrix.x4 (tiles t=0,1), then tf32 hi/lo split
            const uint32_t aaddr = aB32 + (uint32_t)(k0 + 8 * s) * 4u;
            uint32_t ra0[4], ra1[4];
            ldm4(ra0, aaddr);
            ldm4(ra1, aaddr + 16u * PW * 4u);
            uint32_t ah[2][4], al[2][4];
#pragma unroll
            for (int i = 0; i < 4; i++){
                float f0 = __uint_as_float(ra0[i]);
                ah[0][i] = tf32r(f0);
                al[0][i] = tf32r(f0 - __uint_as_float(ah[0][i]));
                float f1 = __uint_as_float(ra1[i]);
                ah[1][i] = tf32r(f1);
                al[1][i] = tf32r(f1 - __uint_as_float(ah[1][i]));
            }

            // B fragments: packed per-lane block, float4 loads (conflict-free)
            const float* blk = bufp + ((size_t)((s * 2 + cgh) * 32 + lane)) * STRIDE;
            float bhv[2 * NTw], blv[2 * NTw];
#pragma unroll
            for (int c = 0; c < NTw / 2; c++){
                *(float4*)&bhv[4 * c] = *(const float4*)(blk + 4 * c);
                *(float4*)&blv[4 * c] = *(const float4*)(blk + CHF + 4 * c);
            }
#pragma unroll
            for (int j = 0; j < NTw; j++){
                uint32_t bhi[2] = { __float_as_uint(bhv[2 * j]),
                                    __float_as_uint(bhv[2 * j + 1]) };
                uint32_t blo[2] = { __float_as_uint(blv[2 * j]),
                                    __float_as_uint(blv[2 * j + 1]) };
                mma8(acc[0][j], ah[0], bhi);
                mma8(acc[0][j], ah[0], blo);
                mma8(acc[0][j], al[0], bhi);
                mma8(acc[1][j], ah[1], bhi);
                mma8(acc[1][j], ah[1], blo);
                mma8(acc[1][j], al[1], bhi);
            }
        }
    }

    // phase 1: relu (+red) into acc; all scratch READS happen here
#pragma unroll
    for (int t = 0; t < 2; t++)
#pragma unroll
        for (int j = 0; j < NTw; j++){
            float v0 = frelu(acc[t][j][0]), v1 = frelu(acc[t][j][1]);
            float v2 = frelu(acc[t][j][2]), v3 = frelu(acc[t][j][3]);
            if constexpr (EPI == 1){
                const int cc = aBase + 2 * cgh * Nw + 16 * j + 4 * qc;
                const float4 qa = *(const float4*)&scr[(rbase + t*16 + qr) * PW + cc];
                const float4 qb = *(const float4*)&scr[(rbase + t*16 + qr + 8) * PW + cc];
                v0 += qa.x + qa.y;  v1 += qa.z + qa.w;
                v2 += qb.x + qb.y;  v3 += qb.z + qb.w;
            }
            if constexpr (ESAVE){
                float* e = eSave + (t * NTw + j) * 4;
                e[0] = v0; e[1] = v1; e[2] = v2; e[3] = v3;
            }
            acc[t][j][0] = v0; acc[t][j][1] = v1; acc[t][j][2] = v2; acc[t][j][3] = v3;
        }

    if constexpr (EPI == 2){
#pragma unroll
        for (int t = 0; t < 2; t++)
#pragma unroll
            for (int j = 0; j < NTw; j++){
                const int col = cgh * Nw + 8 * j + 2 * qc;
                const int g0 = growCta + rbase + t * 16 + qr;
                if (g0 < Ntot)
                    *(float2*)&gout[(size_t)g0 * 32 + col] = make_float2(acc[t][j][0], acc[t][j][1]);
                if (g0 + 8 < Ntot)
                    *(float2*)&gout[(size_t)(g0 + 8) * 32 + col] = make_float2(acc[t][j][2], acc[t][j][3]);
            }
        return;
    }

    __syncthreads();                             // all reads done -> safe to overwrite
#pragma unroll
    for (int t = 0; t < 2; t++)
#pragma unroll
        for (int j = 0; j < NTw; j++){
            const int col = dBase + cgh * Nw + 8 * j + 2 * qc;
            *(float2*)&scr[(rbase + t*16 + qr) * PW + col]     = make_float2(acc[t][j][0], acc[t][j][1]);
            *(float2*)&scr[(rbase + t*16 + qr + 8) * PW + col] = make_float2(acc[t][j][2], acc[t][j][3]);
        }
}

template<int N>
__device__ __forceinline__ void restage(float* __restrict__ scr, int base,
                                        const float* __restrict__ e, int tid){
    constexpr int Nw = N / 2, NTw = N / 16;
    const int lane = tid & 31, warp = tid >> 5;
    const int rg = warp >> 1, cgh = warp & 1;
    const int rbase = rg * 32;
    const int qr = lane >> 2, qc = lane & 3;
#pragma unroll
    for (int t = 0; t < 2; t++)
#pragma unroll
        for (int j = 0; j < NTw; j++){
            const float* ep = e + (t * NTw + j) * 4;
            const int col = base + cgh * Nw + 8 * j + 2 * qc;
            *(float2*)&scr[(rbase + t*16 + qr) * PW + col]     = make_float2(ep[0], ep[1]);
            *(float2*)&scr[(rbase + t*16 + qr + 8) * PW + col] = make_float2(ep[2], ep[3]);
        }
}

__global__ void __launch_bounds__(THREADS, 1)
backbone_mma(const float* __restrict__ feat, float* __restrict__ out, int Ntot)
{
    extern __shared__ float smem[];
    float* scr = smem + OFF_SCRF;
    const int tid = threadIdx.x;
    const int growCta = blockIdx.x * MROWS;
    const uint32_t sb32 = smem_u32(smem);

    // feat[128 rows, 16 ch] -> scratch ch0-15
    {
        const int r = tid >> 1, h = tid & 1;
        const int g = growCta + r;
        float4 f0 = make_float4(0,0,0,0), f1 = f0;
        if (g < Ntot){
            const float4* src = (const float4*)&feat[(size_t)g * 16 + h * 8];
            f0 = src[0]; f1 = src[1];
        }
        *(float4*)&scr[r * PW + h * 8]     = f0;
        *(float4*)&scr[r * PW + h * 8 + 4] = f1;
    }

    float e1r[16], e2r[32];

    // encoder
    stage<16,  32, 0, false>(0,      smem, sb32, 0, 0,   nullptr, nullptr, growCta, Ntot, tid);
    stage<32,  32, 0, true >(1536,   smem, sb32, 0, 0,   e1r,     nullptr, growCta, Ntot, tid);
    stage<32,  64, 0, true >(4608,   smem, sb32, 0, 0,   e2r,     nullptr, growCta, Ntot, tid);
    stage<64, 128, 0, false>(7680,   smem, sb32, 0, 0,   nullptr, nullptr, growCta, Ntot, tid);

    // decoder stage 3: cat3 = [e3 ch0-127 | lat3 ch128-255]
    stage<128,128, 0, false>(17920,  smem, sb32, 0, 128, nullptr, nullptr, growCta, Ntot, tid);
    stage<256,128, 1, false>(38400,  smem, sb32, 0, 0,   nullptr, nullptr, growCta, Ntot, tid);
    stage<128, 64, 0, false>(79360,  smem, sb32, 0, 0,   nullptr, nullptr, growCta, Ntot, tid);

    // decoder stage 2: cat2 = [x2 ch0-63 | lat2 ch64-127]
    restage<64>(scr, 64, e2r, tid);
    stage<64,  64, 0, false>(91648,  smem, sb32, 64, 64, nullptr, nullptr, growCta, Ntot, tid);
    stage<128, 64, 1, false>(97792,  smem, sb32, 0, 0,   nullptr, nullptr, growCta, Ntot, tid);
    stage<64,  32, 0, false>(110080, smem, sb32, 0, 0,   nullptr, nullptr, growCta, Ntot, tid);

    // decoder stage 1: cat1 = [x1 ch0-31 | lat1 ch32-63]
    restage<32>(scr, 32, e1r, tid);
    stage<32,  32, 0, false>(116224, smem, sb32, 32, 32, nullptr, nullptr, growCta, Ntot, tid);
    stage<64,  32, 1, false>(119296, smem, sb32, 0, 0,   nullptr, nullptr, growCta, Ntot, tid);

    // final upsample -> gmem [N, 32]
    stage<32,  32, 2, false>(125440, smem, sb32, 0, 0,   nullptr, out, growCta, Ntot, tid);
}

extern "C" void kernel_launch(void* const* d_in, const int* in_sizes, int n_in,
                              void* d_out, int out_size)
{
    const float* feat = (const float*)d_in[0];
    // d_in[1] = coords — sparse structure only; unused for 1x1 subm convs
    const float* Win = (const float*)d_in[2];
    const float* We1 = (const float*)d_in[3];
    const float* We2 = (const float*)d_in[4];
    const float* We3 = (const float*)d_in[5];
    const float* Wl1 = (const float*)d_in[6];
    const float* Wl2 = (const float*)d_in[7];
    const float* Wl3 = (const float*)d_in[8];
    const float* Wm1 = (const float*)d_in[9];
    const float* Wm2 = (const float*)d_in[10];
    const float* Wm3 = (const float*)d_in[11];
    const float* Wu1 = (const float*)d_in[12];
    const float* Wu2 = (const float*)d_in[13];
    const float* Wu3 = (const float*)d_in[14];

    const int N = in_sizes[0] / 16;

    prep_weights<<<232, 256>>>(Win, We1, We2, We3, Wl1, Wl2, Wl3,
                               Wm1, Wm2, Wm3, Wu1, Wu2, Wu3);

    cudaFuncSetAttribute(backbone_mma,
                         cudaFuncAttributeMaxDynamicSharedMemorySize, SMEM_BYTES);
    const int grid = (N + MROWS - 1) / MROWS;
    backbone_mma<<<grid, THREADS, SMEM_BYTES>>>(feat, (float*)d_out, N);
}

// round 16
// speedup vs baseline: 1.5706x; 1.0905x over previous
#include <cuda_runtime.h>
#include <cstdint>

// Round 16: 3xTF32 mma.sync.
//  vs R15: (1) 2 CTAs/SM — MROWS 64, THREADS 128 (same 32 x N/2 warp tile),
//  KC 16 -> 107.5 KB smem/CTA; the two CTAs run in unrelated phases so one
//  CTA's barriers/cp.async waits overlap the other's MMA bursts.
//  (2) truncation split for A: HMMA.TF32 reads the top 19 bits of the fp32
//  register, so the raw ldmatrix value serves as A_hi; correction is
//  alo = a - (a & 0xFFFFE000) (LOP3+FSUB, no cvt chain).

#define THREADS 128
#define MROWS   64
#define PW      260                    // scratch pitch, ==4 mod 32
#define KC      16
#define MAXCHF  2560                   // per-plane chunk floats (N=128: 2*64*20)
#define BUFTOT  (2 * MAXCHF)           // one buffer: hi + lo planes
#define OFF_SCRF (2 * BUFTOT)          // 10240 floats
#define SMEM_FLOATS (OFF_SCRF + MROWS * PW)
#define SMEM_BYTES  (SMEM_FLOATS * 4)  // 107520 B -> 2 CTAs/SM

#define TOTB 128512
__device__ float g_bhi[TOTB];
__device__ float g_blo[TOTB];

__device__ __forceinline__ uint32_t tf32r(float x){
    uint32_t r; asm("cvt.rna.tf32.f32 %0, %1;" : "=r"(r) : "f"(x)); return r;
}
__device__ __forceinline__ float frelu(float v){ return v > 0.f ? v : 0.f; }
__device__ __forceinline__ uint32_t smem_u32(const void* p){
    uint32_t a;
    asm("{ .reg .u64 t; cvta.to.shared.u64 t, %1; cvt.u32.u64 %0, t; }" : "=r"(a) : "l"(p));
    return a;
}
__device__ __forceinline__ void cpa16(uint32_t s, const float* g){
    asm volatile("cp.async.cg.shared.global [%0], [%1], 16;" :: "r"(s), "l"(g));
}
#define CPA_COMMIT() asm volatile("cp.async.commit_group;" ::: "memory")
#define CPA_WAIT0()  asm volatile("cp.async.wait_group 0;" ::: "memory")

__device__ __forceinline__ void ldm4(uint32_t* r, uint32_t addr){
    asm volatile("ldmatrix.sync.aligned.m8n8.x4.shared.b16 {%0,%1,%2,%3}, [%4];"
        : "=r"(r[0]), "=r"(r[1]), "=r"(r[2]), "=r"(r[3]) : "r"(addr));
}
__device__ __forceinline__ void mma8(float* d, const uint32_t* a, const uint32_t* b){
    asm volatile("mma.sync.aligned.m16n8k8.row.col.f32.tf32.tf32.f32 "
        "{%0,%1,%2,%3},{%4,%5,%6,%7},{%8,%9},{%0,%1,%2,%3};"
        : "+f"(d[0]), "+f"(d[1]), "+f"(d[2]), "+f"(d[3])
        : "r"(a[0]), "r"(a[1]), "r"(a[2]), "r"(a[3]), "r"(b[0]), "r"(b[1]));
}

// -------- prep: pack B fragments per (slice, colhalf, lane) as tf32 hi/lo ----
__global__ void prep_weights(const float* __restrict__ Win,
                             const float* __restrict__ We1, const float* __restrict__ We2,
                             const float* __restrict__ We3,
                             const float* __restrict__ Wl1, const float* __restrict__ Wl2,
                             const float* __restrict__ Wl3,
                             const float* __restrict__ Wm1, const float* __restrict__ Wm2,
                             const float* __restrict__ Wm3,
                             const float* __restrict__ Wu1, const float* __restrict__ Wu2,
                             const float* __restrict__ Wu3)
{
    const float* Ws[13] = {Win, We1, We2, We3, Wl3, Wm3, Wu3, Wl2, Wm2, Wu2, Wl1, Wm1, Wu1};
    const int   Ks[13]  = {16, 32, 32, 64, 128, 256, 128, 64, 128, 64, 32, 64, 32};
    const int   Ns[13]  = {32, 32, 64, 128, 128, 128, 64, 64, 64, 32, 32, 32, 32};
    const int   Os[13]  = {0, 1536, 4608, 7680, 17920, 38400, 79360, 91648, 97792,
                           110080, 116224, 119296, 125440};
    const int gt = blockIdx.x * blockDim.x + threadIdx.x;
    const int gs = gridDim.x * blockDim.x;
#pragma unroll 1
    for (int st = 0; st < 13; st++){
        const int K = Ks[st], N = Ns[st], off = Os[st];
        const int NTw = N / 16;
        const int STRIDE = (NTw == 8) ? 20 : 12;
        const int total = (K / 8) * 64 * STRIDE;
        const float* W = Ws[st];
        for (int e = gt; e < total; e += gs){
            const int b = e / STRIDE, r = e - (e / STRIDE) * STRIDE;
            float hv = 0.f, lv = 0.f;
            if (r < 2 * NTw){
                const int j = r >> 1, p = r & 1;
                const int lane = b & 31, cg = (b >> 5) & 1, s = b >> 6;
                const int qr = lane >> 2, qc = lane & 3;
                const int k = 8 * s + qc + 4 * p;
                const int n = cg * (N / 2) + 8 * j + qr;
                float w = W[k * N + n];
                hv = __uint_as_float(tf32r(w));
                lv = __uint_as_float(tf32r(w - hv));
            }
            g_bhi[off + e] = hv;
            g_blo[off + e] = lv;
        }
    }
}

// -------- main stage ---------------------------------------------------------
// Warp (rg,cgh): rows [rg*32,+32) as 2 m16 tiles, cols [cgh*N/2,+N/2).
// EPI: 0 -> scratch ; 1 -> +pairsum(cat) -> scratch ; 2 -> gmem [*,32].
template<int K, int N, int EPI, bool ESAVE>
__device__ __forceinline__ void stage(int woff,
                                      float* __restrict__ smem, uint32_t sb32,
                                      int aBase, int dBase,
                                      float* __restrict__ eSave,
                                      float* __restrict__ gout,
                                      int growCta, int Ntot, int tid)
{
    constexpr int Nw  = N / 2;
    constexpr int NTw = N / 16;
    constexpr int STRIDE = (NTw == 8) ? 20 : 12;
    constexpr int KcC = (K < KC) ? K : KC;
    constexpr int NCH = K / KcC;
    constexpr int SLC = KcC / 8;                 // slices per chunk
    constexpr int CHF = SLC * 64 * STRIDE;       // per-plane chunk floats
    const int lane = tid & 31;
    const int warp = tid >> 5;
    const int rg   = warp >> 1;                  // 0..1
    const int cgh  = warp & 1;
    const int rbase = rg * 32;
    const int qr = lane >> 2, qc = lane & 3;
    float* scr = smem + OFF_SCRF;

    const int rowA   = (lane & 7) + ((lane >> 3) & 1) * 8;
    const int colSel = (lane >> 4) & 1;
    const uint32_t aB32 = sb32 + (uint32_t)(OFF_SCRF + (rbase + rowA) * PW
                                            + aBase + 4 * colSel) * 4u;

    float acc[2][NTw][4];
#pragma unroll
    for (int t = 0; t < 2; t++)
#pragma unroll
        for (int j = 0; j < NTw; j++){ acc[t][j][0]=acc[t][j][1]=acc[t][j][2]=acc[t][j][3]=0.f; }

    // issue chunk 0 into buffer 0
    {
        const float* gh = g_bhi + woff;
        const float* gl = g_blo + woff;
        for (int i = tid * 4; i < CHF; i += THREADS * 4){
            cpa16(sb32 + i * 4, gh + i);
            cpa16(sb32 + (CHF + i) * 4, gl + i);
        }
        CPA_COMMIT();
    }

    for (int ch = 0; ch < NCH; ch++){
        const int b = ch & 1;
        CPA_WAIT0();
        __syncthreads();
        if (ch + 1 < NCH){
            const int nb = (ch + 1) & 1;
            const float* gh = g_bhi + woff + (ch + 1) * CHF;
            const float* gl = g_blo + woff + (ch + 1) * CHF;
            const uint32_t sh = sb32 + (uint32_t)nb * (BUFTOT * 4);
            for (int i = tid * 4; i < CHF; i += THREADS * 4){
                cpa16(sh + i * 4, gh + i);
                cpa16(sh + (CHF + i) * 4, gl + i);
            }
            CPA_COMMIT();
        }

        const float* bufp = smem + b * BUFTOT;
        const int k0 = ch * KcC;
#pragma unroll
        for (int s = 0; s < SLC; s++){
            // A fragments: raw fp32 serves as hi operand (HW truncates to tf32);
            // correction alo = a - (a & 0xFFFFE000)
            const uint32_t aaddr = aB32 + (uint32_t)(k0 + 8 * s) * 4u;
            uint32_t ah[2][4], al[2][4];
            ldm4(ah[0], aaddr);
            ldm4(ah[1], aaddr + 16u * PW * 4u);
#pragma unroll
            for (int t = 0; t < 2; t++)
#pragma unroll
                for (int i = 0; i < 4; i++){
                    const uint32_t m = ah[t][i] & 0xFFFFE000u;
                    al[t][i] = __float_as_uint(__uint_as_float(ah[t][i]) - __uint_as_float(m));
                }

            // B fragments: packed per-lane block, float4 loads (conflict-free)
            const float* blk = bufp + ((size_t)(((s - 0) * 2 + cgh) * 32 + lane)) * STRIDE;
            float bhv[2 * NTw], blv[2 * NTw];
#pragma unroll
            for (int c = 0; c < NTw / 2; c++){
                *(float4*)&bhv[4 * c] = *(const float4*)(blk + 4 * c);
                *(float4*)&blv[4 * c] = *(const float4*)(blk + CHF + 4 * c);
            }
#pragma unroll
            for (int j = 0; j < NTw; j++){
                uint32_t bhi[2] = { __float_as_uint(bhv[2 * j]),
                                    __float_as_uint(bhv[2 * j + 1]) };
                uint32_t blo[2] = { __float_as_uint(blv[2 * j]),
                                    __float_as_uint(blv[2 * j + 1]) };
                mma8(acc[0][j], ah[0], bhi);
                mma8(acc[0][j], ah[0], blo);
                mma8(acc[0][j], al[0], bhi);
                mma8(acc[1][j], ah[1], bhi);
                mma8(acc[1][j], ah[1], blo);
                mma8(acc[1][j], al[1], bhi);
            }
        }
    }

    // phase 1: relu (+red) into acc; all scratch READS happen here
#pragma unroll
    for (int t = 0; t < 2; t++)
#pragma unroll
        for (int j = 0; j < NTw; j++){
            float v0 = frelu(acc[t][j][0]), v1 = frelu(acc[t][j][1]);
            float v2 = frelu(acc[t][j][2]), v3 = frelu(acc[t][j][3]);
            if constexpr (EPI == 1){
                const int cc = aBase + 2 * cgh * Nw + 16 * j + 4 * qc;
                const float4 qa = *(const float4*)&scr[(rbase + t*16 + qr) * PW + cc];
                const float4 qb = *(const float4*)&scr[(rbase + t*16 + qr + 8) * PW + cc];
                v0 += qa.x + qa.y;  v1 += qa.z + qa.w;
                v2 += qb.x + qb.y;  v3 += qb.z + qb.w;
            }
            if constexpr (ESAVE){
                float* e = eSave + (t * NTw + j) * 4;
                e[0] = v0; e[1] = v1; e[2] = v2; e[3] = v3;
            }
            acc[t][j][0] = v0; acc[t][j][1] = v1; acc[t][j][2] = v2; acc[t][j][3] = v3;
        }

    if constexpr (EPI == 2){
#pragma unroll
        for (int t = 0; t < 2; t++)
#pragma unroll
            for (int j = 0; j < NTw; j++){
                const int col = cgh * Nw + 8 * j + 2 * qc;
                const int g0 = growCta + rbase + t * 16 + qr;
                if (g0 < Ntot)
                    *(float2*)&gout[(size_t)g0 * 32 + col] = make_float2(acc[t][j][0], acc[t][j][1]);
                if (g0 + 8 < Ntot)
                    *(float2*)&gout[(size_t)(g0 + 8) * 32 + col] = make_float2(acc[t][j][2], acc[t][j][3]);
            }
        return;
    }

    __syncthreads();                             // all reads done -> safe to overwrite
#pragma unroll
    for (int t = 0; t < 2; t++)
#pragma unroll
        for (int j = 0; j < NTw; j++){
            const int col = dBase + cgh * Nw + 8 * j + 2 * qc;
            *(float2*)&scr[(rbase + t*16 + qr) * PW + col]     = make_float2(acc[t][j][0], acc[t][j][1]);
            *(float2*)&scr[(rbase + t*16 + qr + 8) * PW + col] = make_float2(acc[t][j][2], acc[t][j][3]);
        }
}

template<int N>
__device__ __forceinline__ void restage(float* __restrict__ scr, int base,
                                        const float* __restrict__ e, int tid){
    constexpr int Nw = N / 2, NTw = N / 16;
    const int lane = tid & 31, warp = tid >> 5;
    const int rg = warp >> 1, cgh = warp & 1;
    const int rbase = rg * 32;
    const int qr = lane >> 2, qc = lane & 3;
#pragma unroll
    for (int t = 0; t < 2; t++)
#pragma unroll
        for (int j = 0; j < NTw; j++){
            const float* ep = e + (t * NTw + j) * 4;
            const int col = base + cgh * Nw + 8 * j + 2 * qc;
            *(float2*)&scr[(rbase + t*16 + qr) * PW + col]     = make_float2(ep[0], ep[1]);
            *(float2*)&scr[(rbase + t*16 + qr + 8) * PW + col] = make_float2(ep[2], ep[3]);
        }
}

__global__ void __launch_bounds__(THREADS, 2)
backbone_mma(const float* __restrict__ feat, float* __restrict__ out, int Ntot)
{
    extern __shared__ float smem[];
    float* scr = smem + OFF_SCRF;
    const int tid = threadIdx.x;
    const int growCta = blockIdx.x * MROWS;
    const uint32_t sb32 = smem_u32(smem);

    // feat[64 rows, 16 ch] -> scratch ch0-15
    {
        const int r = tid >> 1, h = tid & 1;
        const int g = growCta + r;
        float4 f0 = make_float4(0,0,0,0), f1 = f0;
        if (g < Ntot){
            const float4* src = (const float4*)&feat[(size_t)g * 16 + h * 8];
            f0 = src[0]; f1 = src[1];
        }
        *(float4*)&scr[r * PW + h * 8]     = f0;
        *(float4*)&scr[r * PW + h * 8 + 4] = f1;
    }

    float e1r[16], e2r[32];

    // encoder
    stage<16,  32, 0, false>(0,      smem, sb32, 0, 0,   nullptr, nullptr, growCta, Ntot, tid);
    stage<32,  32, 0, true >(1536,   smem, sb32, 0, 0,   e1r,     nullptr, growCta, Ntot, tid);
    stage<32,  64, 0, true >(4608,   smem, sb32, 0, 0,   e2r,     nullptr, growCta, Ntot, tid);
    stage<64, 128, 0, false>(7680,   smem, sb32, 0, 0,   nullptr, nullptr, growCta, Ntot, tid);

    // decoder stage 3: cat3 = [e3 ch0-127 | lat3 ch128-255]
    stage<128,128, 0, false>(17920,  smem, sb32, 0, 128, nullptr, nullptr, growCta, Ntot, tid);
    stage<256,128, 1, false>(38400,  smem, sb32, 0, 0,   nullptr, nullptr, growCta, Ntot, tid);
    stage<128, 64, 0, false>(79360,  smem, sb32, 0, 0,   nullptr, nullptr, growCta, Ntot, tid);

    // decoder stage 2: cat2 = [x2 ch0-63 | lat2 ch64-127]
    restage<64>(scr, 64, e2r, tid);
    stage<64,  64, 0, false>(91648,  smem, sb32, 64, 64, nullptr, nullptr, growCta, Ntot, tid);
    stage<128, 64, 1, false>(97792,  smem, sb32, 0, 0,   nullptr, nullptr, growCta, Ntot, tid);
    stage<64,  32, 0, false>(110080, smem, sb32, 0, 0,   nullptr, nullptr, growCta, Ntot, tid);

    // decoder stage 1: cat1 = [x1 ch0-31 | lat1 ch32-63]
    restage<32>(scr, 32, e1r, tid);
    stage<32,  32, 0, false>(116224, smem, sb32, 32, 32, nullptr, nullptr, growCta, Ntot, tid);
    stage<64,  32, 1, false>(119296, smem, sb32, 0, 0,   nullptr, nullptr, growCta, Ntot, tid);

    // final upsample -> gmem [N, 32]
    stage<32,  32, 2, false>(125440, smem, sb32, 0, 0,   nullptr, out, growCta, Ntot, tid);
}

extern "C" void kernel_launch(void* const* d_in, const int* in_sizes, int n_in,
                              void* d_out, int out_size)
{
    const float* feat = (const float*)d_in[0];
    // d_in[1] = coords — sparse structure only; unused for 1x1 subm convs
    const float* Win = (const float*)d_in[2];
    const float* We1 = (const float*)d_in[3];
    const float* We2 = (const float*)d_in[4];
    const float* We3 = (const float*)d_in[5];
    const float* Wl1 = (const float*)d_in[6];
    const float* Wl2 = (const float*)d_in[7];
    const float* Wl3 = (const float*)d_in[8];
    const float* Wm1 = (const float*)d_in[9];
    const float* Wm2 = (const float*)d_in[10];
    const float* Wm3 = (const float*)d_in[11];
    const float* Wu1 = (const float*)d_in[12];
    const float* Wu2 = (const float*)d_in[13];
    const float* Wu3 = (const float*)d_in[14];

    const int N = in_sizes[0] / 16;

    prep_weights<<<232, 256>>>(Win, We1, We2, We3, Wl1, Wl2, Wl3,
                               Wm1, Wm2, Wm3, Wu1, Wu2, Wu3);

    cudaFuncSetAttribute(backbone_mma,
                         cudaFuncAttributeMaxDynamicSharedMemorySize, SMEM_BYTES);
    const int grid = (N + MROWS - 1) / MROWS;
    backbone_mma<<<grid, THREADS, SMEM_BYTES>>>(feat, (float*)d_out, N);
}

// round 17
// speedup vs baseline: 1.8235x; 1.1610x over previous
#include <cuda_runtime.h>
#include <cstdint>

// Round 17: 2-MMA-per-slice split GEMM.
//  main:       tf32 m16n8k8  D += trunc(A)*Bhi          (HW truncates raw A)
//  correction: f16  m16n8k16 D += Ahi*Blo + Alo*Bhi     (vk16 interleave:
//              vk=2k -> (Ahi,Blo), vk=2k+1 -> (Alo,Bhi); per-lane real-k map
//              identical to the tf32 fragments -> no shuffles, only f16x2 cvt)
//  B planes: fp32 Bhi (tf32-rounded) + packed f16x2 {lo=Blo, hi=Bhi}.
//  Everything else (2 CTAs/SM, cp.async double buffer, prep pass) = R16.

#define THREADS 128
#define MROWS   64
#define PW      260                    // scratch pitch, ==4 mod 32
#define KC      16
#define MAXCHF  2560                   // per-plane chunk elems (N=128: 2*64*20)
#define BUFTOT  (2 * MAXCHF)           // one buffer: hi(f32) + corr(u32) planes
#define OFF_SCRF (2 * BUFTOT)          // 10240 elems
#define SMEM_FLOATS (OFF_SCRF + MROWS * PW)
#define SMEM_BYTES  (SMEM_FLOATS * 4)  // 107520 B -> 2 CTAs/SM

#define TOTB 128512
__device__ float    g_bhi[TOTB];
__device__ uint32_t g_bc[TOTB];        // f16x2 {lo=Blo, hi=Bhi}

__device__ __forceinline__ uint32_t tf32r(float x){
    uint32_t r; asm("cvt.rna.tf32.f32 %0, %1;" : "=r"(r) : "f"(x)); return r;
}
__device__ __forceinline__ uint32_t h2pack(float hi, float lo){
    uint32_t r; asm("cvt.rn.f16x2.f32 %0, %1, %2;" : "=r"(r) : "f"(hi), "f"(lo)); return r;
}
__device__ __forceinline__ float frelu(float v){ return v > 0.f ? v : 0.f; }
__device__ __forceinline__ uint32_t smem_u32(const void* p){
    uint32_t a;
    asm("{ .reg .u64 t; cvta.to.shared.u64 t, %1; cvt.u32.u64 %0, t; }" : "=r"(a) : "l"(p));
    return a;
}
__device__ __forceinline__ void cpa16(uint32_t s, const void* g){
    asm volatile("cp.async.cg.shared.global [%0], [%1], 16;" :: "r"(s), "l"(g));
}
#define CPA_COMMIT() asm volatile("cp.async.commit_group;" ::: "memory")
#define CPA_WAIT0()  asm volatile("cp.async.wait_group 0;" ::: "memory")

__device__ __forceinline__ void ldm4(uint32_t* r, uint32_t addr){
    asm volatile("ldmatrix.sync.aligned.m8n8.x4.shared.b16 {%0,%1,%2,%3}, [%4];"
        : "=r"(r[0]), "=r"(r[1]), "=r"(r[2]), "=r"(r[3]) : "r"(addr));
}
__device__ __forceinline__ void mma8(float* d, const uint32_t* a, const uint32_t* b){
    asm volatile("mma.sync.aligned.m16n8k8.row.col.f32.tf32.tf32.f32 "
        "{%0,%1,%2,%3},{%4,%5,%6,%7},{%8,%9},{%0,%1,%2,%3};"
        : "+f"(d[0]), "+f"(d[1]), "+f"(d[2]), "+f"(d[3])
        : "r"(a[0]), "r"(a[1]), "r"(a[2]), "r"(a[3]), "r"(b[0]), "r"(b[1]));
}
__device__ __forceinline__ void mma16h(float* d, const uint32_t* a, uint32_t b0, uint32_t b1){
    asm volatile("mma.sync.aligned.m16n8k16.row.col.f32.f16.f16.f32 "
        "{%0,%1,%2,%3},{%4,%5,%6,%7},{%8,%9},{%0,%1,%2,%3};"
        : "+f"(d[0]), "+f"(d[1]), "+f"(d[2]), "+f"(d[3])
        : "r"(a[0]), "r"(a[1]), "r"(a[2]), "r"(a[3]), "r"(b0), "r"(b1));
}

// -------- prep: pack B fragment planes per (slice, colhalf, lane) ------------
__global__ void prep_weights(const float* __restrict__ Win,
                             const float* __restrict__ We1, const float* __restrict__ We2,
                             const float* __restrict__ We3,
                             const float* __restrict__ Wl1, const float* __restrict__ Wl2,
                             const float* __restrict__ Wl3,
                             const float* __restrict__ Wm1, const float* __restrict__ Wm2,
                             const float* __restrict__ Wm3,
                             const float* __restrict__ Wu1, const float* __restrict__ Wu2,
                             const float* __restrict__ Wu3)
{
    const float* Ws[13] = {Win, We1, We2, We3, Wl3, Wm3, Wu3, Wl2, Wm2, Wu2, Wl1, Wm1, Wu1};
    const int   Ks[13]  = {16, 32, 32, 64, 128, 256, 128, 64, 128, 64, 32, 64, 32};
    const int   Ns[13]  = {32, 32, 64, 128, 128, 128, 64, 64, 64, 32, 32, 32, 32};
    const int   Os[13]  = {0, 1536, 4608, 7680, 17920, 38400, 79360, 91648, 97792,
                           110080, 116224, 119296, 125440};
    const int gt = blockIdx.x * blockDim.x + threadIdx.x;
    const int gs = gridDim.x * blockDim.x;
#pragma unroll 1
    for (int st = 0; st < 13; st++){
        const int K = Ks[st], N = Ns[st], off = Os[st];
        const int NTw = N / 16;
        const int STRIDE = (NTw == 8) ? 20 : 12;
        const int total = (K / 8) * 64 * STRIDE;
        const float* W = Ws[st];
        for (int e = gt; e < total; e += gs){
            const int b = e / STRIDE, r = e - (e / STRIDE) * STRIDE;
            float hv = 0.f, lv = 0.f;
            if (r < 2 * NTw){
                const int j = r >> 1, p = r & 1;
                const int lane = b & 31, cg = (b >> 5) & 1, s = b >> 6;
                const int qr = lane >> 2, qc = lane & 3;
                const int k = 8 * s + qc + 4 * p;
                const int n = cg * (N / 2) + 8 * j + qr;
                float w = W[k * N + n];
                hv = __uint_as_float(tf32r(w));
                lv = w - hv;
            }
            g_bhi[off + e] = hv;
            g_bc[off + e]  = h2pack(hv, lv);   // hi half = Bhi, lo half = Blo
        }
    }
}

// -------- main stage ---------------------------------------------------------
// Warp (rg,cgh): rows [rg*32,+32) as 2 m16 tiles, cols [cgh*N/2,+N/2).
// EPI: 0 -> scratch ; 1 -> +pairsum(cat) -> scratch ; 2 -> gmem [*,32].
template<int K, int N, int EPI, bool ESAVE>
__device__ __forceinline__ void stage(int woff,
                                      float* __restrict__ smem, uint32_t sb32,
                                      int aBase, int dBase,
                                      float* __restrict__ eSave,
                                      float* __restrict__ gout,
                                      int growCta, int Ntot, int tid)
{
    constexpr int Nw  = N / 2;
    constexpr int NTw = N / 16;
    constexpr int STRIDE = (NTw == 8) ? 20 : 12;
    constexpr int KcC = (K < KC) ? K : KC;
    constexpr int NCH = K / KcC;
    constexpr int SLC = KcC / 8;
    constexpr int CHF = SLC * 64 * STRIDE;       // per-plane chunk elems
    const int lane = tid & 31;
    const int warp = tid >> 5;
    const int rg   = warp >> 1;
    const int cgh  = warp & 1;
    const int rbase = rg * 32;
    const int qr = lane >> 2, qc = lane & 3;
    float* scr = smem + OFF_SCRF;

    const int rowA   = (lane & 7) + ((lane >> 3) & 1) * 8;
    const int colSel = (lane >> 4) & 1;
    const uint32_t aB32 = sb32 + (uint32_t)(OFF_SCRF + (rbase + rowA) * PW
                                            + aBase + 4 * colSel) * 4u;

    float acc[2][NTw][4];
#pragma unroll
    for (int t = 0; t < 2; t++)
#pragma unroll
        for (int j = 0; j < NTw; j++){ acc[t][j][0]=acc[t][j][1]=acc[t][j][2]=acc[t][j][3]=0.f; }

    // issue chunk 0 into buffer 0
    {
        const float* gh = g_bhi + woff;
        const uint32_t* gc = g_bc + woff;
        for (int i = tid * 4; i < CHF; i += THREADS * 4){
            cpa16(sb32 + i * 4, gh + i);
            cpa16(sb32 + (CHF + i) * 4, gc + i);
        }
        CPA_COMMIT();
    }

    for (int ch = 0; ch < NCH; ch++){
        const int b = ch & 1;
        CPA_WAIT0();
        __syncthreads();
        if (ch + 1 < NCH){
            const int nb = (ch + 1) & 1;
            const float* gh = g_bhi + woff + (ch + 1) * CHF;
            const uint32_t* gc = g_bc + woff + (ch + 1) * CHF;
            const uint32_t sh = sb32 + (uint32_t)nb * (BUFTOT * 4);
            for (int i = tid * 4; i < CHF; i += THREADS * 4){
                cpa16(sh + i * 4, gh + i);
                cpa16(sh + (CHF + i) * 4, gc + i);
            }
            CPA_COMMIT();
        }

        const float* bufp = smem + b * BUFTOT;
        const uint32_t* bufc = (const uint32_t*)(bufp + CHF);
        const int k0 = ch * KcC;
#pragma unroll
        for (int s = 0; s < SLC; s++){
            // A: raw fp32 is the tf32-hi operand (HW truncates);
            // alo = a - (a & 0xFFFFE000); f16 frag = {lo=Ahi, hi=Alo} pairs
            const uint32_t aaddr = aB32 + (uint32_t)(k0 + 8 * s) * 4u;
            uint32_t ah[2][4], fa[2][4];
            ldm4(ah[0], aaddr);
            ldm4(ah[1], aaddr + 16u * PW * 4u);
#pragma unroll
            for (int t = 0; t < 2; t++)
#pragma unroll
                for (int i = 0; i < 4; i++){
                    const uint32_t m = ah[t][i] & 0xFFFFE000u;
                    const float mf = __uint_as_float(m);
                    const float al = __uint_as_float(ah[t][i]) - mf;
                    fa[t][i] = h2pack(al, mf);          // hi=Alo, lo=Ahi
                }

            // B fragments: hi plane (fp32) + corr plane (f16x2), float4 loads
            const float* blk = bufp + ((size_t)((s * 2 + cgh) * 32 + lane)) * STRIDE;
            const uint32_t* blkc = bufc + ((size_t)((s * 2 + cgh) * 32 + lane)) * STRIDE;
            float bhv[2 * NTw];
            uint32_t bcv[2 * NTw];
#pragma unroll
            for (int c = 0; c < NTw / 2; c++){
                *(float4*)&bhv[4 * c] = *(const float4*)(blk + 4 * c);
                *(uint4*)&bcv[4 * c]  = *(const uint4*)(blkc + 4 * c);
            }
#pragma unroll
            for (int j = 0; j < NTw; j++){
                uint32_t bhi[2] = { __float_as_uint(bhv[2 * j]),
                                    __float_as_uint(bhv[2 * j + 1]) };
                mma8 (acc[0][j], ah[0], bhi);
                mma16h(acc[0][j], fa[0], bcv[2 * j], bcv[2 * j + 1]);
                mma8 (acc[1][j], ah[1], bhi);
                mma16h(acc[1][j], fa[1], bcv[2 * j], bcv[2 * j + 1]);
            }
        }
    }

    // phase 1: relu (+red) into acc; all scratch READS happen here
#pragma unroll
    for (int t = 0; t < 2; t++)
#pragma unroll
        for (int j = 0; j < NTw; j++){
            float v0 = frelu(acc[t][j][0]), v1 = frelu(acc[t][j][1]);
            float v2 = frelu(acc[t][j][2]), v3 = frelu(acc[t][j][3]);
            if constexpr (EPI == 1){
                const int cc = aBase + 2 * cgh * Nw + 16 * j + 4 * qc;
                const float4 qa = *(const float4*)&scr[(rbase + t*16 + qr) * PW + cc];
                const float4 qb = *(const float4*)&scr[(rbase + t*16 + qr + 8) * PW + cc];
                v0 += qa.x + qa.y;  v1 += qa.z + qa.w;
                v2 += qb.x + qb.y;  v3 += qb.z + qb.w;
            }
            if constexpr (ESAVE){
                float* e = eSave + (t * NTw + j) * 4;
                e[0] = v0; e[1] = v1; e[2] = v2; e[3] = v3;
            }
            acc[t][j][0] = v0; acc[t][j][1] = v1; acc[t][j][2] = v2; acc[t][j][3] = v3;
        }

    if constexpr (EPI == 2){
#pragma unroll
        for (int t = 0; t < 2; t++)
#pragma unroll
            for (int j = 0; j < NTw; j++){
                const int col = cgh * Nw + 8 * j + 2 * qc;
                const int g0 = growCta + rbase + t * 16 + qr;
                if (g0 < Ntot)
                    *(float2*)&gout[(size_t)g0 * 32 + col] = make_float2(acc[t][j][0], acc[t][j][1]);
                if (g0 + 8 < Ntot)
                    *(float2*)&gout[(size_t)(g0 + 8) * 32 + col] = make_float2(acc[t][j][2], acc[t][j][3]);
            }
        return;
    }

    __syncthreads();                             // all reads done -> safe to overwrite
#pragma unroll
    for (int t = 0; t < 2; t++)
#pragma unroll
        for (int j = 0; j < NTw; j++){
            const int col = dBase + cgh * Nw + 8 * j + 2 * qc;
            *(float2*)&scr[(rbase + t*16 + qr) * PW + col]     = make_float2(acc[t][j][0], acc[t][j][1]);
            *(float2*)&scr[(rbase + t*16 + qr + 8) * PW + col] = make_float2(acc[t][j][2], acc[t][j][3]);
        }
}

template<int N>
__device__ __forceinline__ void restage(float* __restrict__ scr, int base,
                                        const float* __restrict__ e, int tid){
    constexpr int Nw = N / 2, NTw = N / 16;
    const int lane = tid & 31, warp = tid >> 5;
    const int rg = warp >> 1, cgh = warp & 1;
    const int rbase = rg * 32;
    const int qr = lane >> 2, qc = lane & 3;
#pragma unroll
    for (int t = 0; t < 2; t++)
#pragma unroll
        for (int j = 0; j < NTw; j++){
            const float* ep = e + (t * NTw + j) * 4;
            const int col = base + cgh * Nw + 8 * j + 2 * qc;
            *(float2*)&scr[(rbase + t*16 + qr) * PW + col]     = make_float2(ep[0], ep[1]);
            *(float2*)&scr[(rbase + t*16 + qr + 8) * PW + col] = make_float2(ep[2], ep[3]);
        }
}

__global__ void __launch_bounds__(THREADS, 2)
backbone_mma(const float* __restrict__ feat, float* __restrict__ out, int Ntot)
{
    extern __shared__ float smem[];
    float* scr = smem + OFF_SCRF;
    const int tid = threadIdx.x;
    const int growCta = blockIdx.x * MROWS;
    const uint32_t sb32 = smem_u32(smem);

    // feat[64 rows, 16 ch] -> scratch ch0-15
    {
        const int r = tid >> 1, h = tid & 1;
        const int g = growCta + r;
        float4 f0 = make_float4(0,0,0,0), f1 = f0;
        if (g < Ntot){
            const float4* src = (const float4*)&feat[(size_t)g * 16 + h * 8];
            f0 = src[0]; f1 = src[1];
        }
        *(float4*)&scr[r * PW + h * 8]     = f0;
        *(float4*)&scr[r * PW + h * 8 + 4] = f1;
    }

    float e1r[16], e2r[32];

    // encoder
    stage<16,  32, 0, false>(0,      smem, sb32, 0, 0,   nullptr, nullptr, growCta, Ntot, tid);
    stage<32,  32, 0, true >(1536,   smem, sb32, 0, 0,   e1r,     nullptr, growCta, Ntot, tid);
    stage<32,  64, 0, true >(4608,   smem, sb32, 0, 0,   e2r,     nullptr, growCta, Ntot, tid);
    stage<64, 128, 0, false>(7680,   smem, sb32, 0, 0,   nullptr, nullptr, growCta, Ntot, tid);

    // decoder stage 3: cat3 = [e3 ch0-127 | lat3 ch128-255]
    stage<128,128, 0, false>(17920,  smem, sb32, 0, 128, nullptr, nullptr, growCta, Ntot, tid);
    stage<256,128, 1, false>(38400,  smem, sb32, 0, 0,   nullptr, nullptr, growCta, Ntot, tid);
    stage<128, 64, 0, false>(79360,  smem, sb32, 0, 0,   nullptr, nullptr, growCta, Ntot, tid);

    // decoder stage 2: cat2 = [x2 ch0-63 | lat2 ch64-127]
    restage<64>(scr, 64, e2r, tid);
    stage<64,  64, 0, false>(91648,  smem, sb32, 64, 64, nullptr, nullptr, growCta, Ntot, tid);
    stage<128, 64, 1, false>(97792,  smem, sb32, 0, 0,   nullptr, nullptr, growCta, Ntot, tid);
    stage<64,  32, 0, false>(110080, smem, sb32, 0, 0,   nullptr, nullptr, growCta, Ntot, tid);

    // decoder stage 1: cat1 = [x1 ch0-31 | lat1 ch32-63]
    restage<32>(scr, 32, e1r, tid);
    stage<32,  32, 0, false>(116224, smem, sb32, 32, 32, nullptr, nullptr, growCta, Ntot, tid);
    stage<64,  32, 1, false>(119296, smem, sb32, 0, 0,   nullptr, nullptr, growCta, Ntot, tid);

    // final upsample -> gmem [N, 32]
    stage<32,  32, 2, false>(125440, smem, sb32, 0, 0,   nullptr, out, growCta, Ntot, tid);
}

extern "C" void kernel_launch(void* const* d_in, const int* in_sizes, int n_in,
                              void* d_out, int out_size)
{
    const float* feat = (const float*)d_in[0];
    // d_in[1] = coords — sparse structure only; unused for 1x1 subm convs
    const float* Win = (const float*)d_in[2];
    const float* We1 = (const float*)d_in[3];
    const float* We2 = (const float*)d_in[4];
    const float* We3 = (const float*)d_in[5];
    const float* Wl1 = (const float*)d_in[6];
    const float* Wl2 = (const float*)d_in[7];
    const float* Wl3 = (const float*)d_in[8];
    const float* Wm1 = (const float*)d_in[9];
    const float* Wm2 = (const float*)d_in[10];
    const float* Wm3 = (const float*)d_in[11];
    const float* Wu1 = (const float*)d_in[12];
    const float* Wu2 = (const float*)d_in[13];
    const float* Wu3 = (const float*)d_in[14];

    const int N = in_sizes[0] / 16;

    prep_weights<<<232, 256>>>(Win, We1, We2, We3, Wl1, Wl2, Wl3,
                               Wm1, Wm2, Wm3, Wu1, Wu2, Wu3);

    cudaFuncSetAttribute(backbone_mma,
                         cudaFuncAttributeMaxDynamicSharedMemorySize, SMEM_BYTES);
    const int grid = (N + MROWS - 1) / MROWS;
    backbone_mma<<<grid, THREADS, SMEM_BYTES>>>(feat, (float*)d_out, N);
}